// round 1
// baseline (speedup 1.0000x reference)
#include <cuda_runtime.h>
#include <cuda_bf16.h>
#include <math.h>

// ---------------------------------------------------------------------------
// Problem constants
// ---------------------------------------------------------------------------
#define BATCH   2
#define SEQ     2048
#define DMODEL  1024
#define DFF     4096
#define NHEADS  16
#define DHEAD   64
#define ROWS    (BATCH * SEQ)            // 4096
#define LN_EPS  1e-5f

// ---------------------------------------------------------------------------
// Scratch (no cudaMalloc allowed) — __device__ globals
// ---------------------------------------------------------------------------
__device__ float g_qkv [(size_t)ROWS * 3 * DMODEL];   // 50 MB
__device__ float g_attn[(size_t)ROWS * DMODEL];       // 16 MB
__device__ float g_h1  [(size_t)ROWS * DMODEL];       // 16 MB
__device__ float g_tmp [(size_t)ROWS * DMODEL];       // 16 MB
__device__ float g_ffn [(size_t)ROWS * DFF];          // 67 MB

// ---------------------------------------------------------------------------
// SGEMM: C[M,N] = act(A[M,K] @ B[K,N] + bias[N])
// Row-major. BM=BN=128, BK=8, 256 threads, 8x8 per thread.
// Requires M%128==0, N%128==0, K%8==0 (true for all calls here).
// act: 0 = none, 1 = exact GELU
// ---------------------------------------------------------------------------
__global__ __launch_bounds__(256, 2)
void sgemm_kernel(const float* __restrict__ A, const float* __restrict__ B,
                  const float* __restrict__ bias, float* __restrict__ C,
                  int M, int N, int K, int act)
{
    __shared__ float As[8][128];
    __shared__ float Bs[8][128];

    const int bx  = blockIdx.x;      // N tile
    const int by  = blockIdx.y;      // M tile
    const int tid = threadIdx.x;
    const int tx  = tid & 15;        // 0..15 -> 8 cols each
    const int ty  = tid >> 4;        // 0..15 -> 8 rows each

    // load indices
    const int a_r  = tid >> 1;            // 0..127
    const int a_k  = (tid & 1) * 4;       // 0 or 4
    const int b_k  = tid >> 5;            // 0..7
    const int b_c  = (tid & 31) * 4;      // 0..124

    const float* Aptr = A + (size_t)(by * 128 + a_r) * K + a_k;
    const float* Bptr = B + (size_t)b_k * N + bx * 128 + b_c;

    float acc[8][8];
#pragma unroll
    for (int i = 0; i < 8; i++)
#pragma unroll
        for (int j = 0; j < 8; j++) acc[i][j] = 0.f;

    for (int k0 = 0; k0 < K; k0 += 8) {
        float4 av = *(const float4*)(Aptr + k0);
        As[a_k + 0][a_r] = av.x;
        As[a_k + 1][a_r] = av.y;
        As[a_k + 2][a_r] = av.z;
        As[a_k + 3][a_r] = av.w;
        *(float4*)&Bs[b_k][b_c] = *(const float4*)(Bptr + (size_t)k0 * N);
        __syncthreads();

#pragma unroll
        for (int k = 0; k < 8; k++) {
            float ar[8], br[8];
#pragma unroll
            for (int i = 0; i < 8; i++) ar[i] = As[k][ty * 8 + i];
#pragma unroll
            for (int j = 0; j < 8; j++) br[j] = Bs[k][tx * 8 + j];
#pragma unroll
            for (int i = 0; i < 8; i++)
#pragma unroll
                for (int j = 0; j < 8; j++)
                    acc[i][j] = fmaf(ar[i], br[j], acc[i][j]);
        }
        __syncthreads();
    }

    // epilogue
    float bv[8];
#pragma unroll
    for (int j = 0; j < 8; j++) bv[j] = bias[bx * 128 + tx * 8 + j];

#pragma unroll
    for (int i = 0; i < 8; i++) {
        float* cp = C + (size_t)(by * 128 + ty * 8 + i) * N + bx * 128 + tx * 8;
#pragma unroll
        for (int j = 0; j < 8; j += 4) {
            float4 v;
            v.x = acc[i][j + 0] + bv[j + 0];
            v.y = acc[i][j + 1] + bv[j + 1];
            v.z = acc[i][j + 2] + bv[j + 2];
            v.w = acc[i][j + 3] + bv[j + 3];
            if (act == 1) {
                v.x = 0.5f * v.x * (1.f + erff(v.x * 0.70710678118654752f));
                v.y = 0.5f * v.y * (1.f + erff(v.y * 0.70710678118654752f));
                v.z = 0.5f * v.z * (1.f + erff(v.z * 0.70710678118654752f));
                v.w = 0.5f * v.w * (1.f + erff(v.w * 0.70710678118654752f));
            }
            *(float4*)(cp + j) = v;
        }
    }
}

// ---------------------------------------------------------------------------
// Flash attention (fp32, causal). One block per (q-tile of 64, head, batch).
// 128 threads: thread t -> query qi = t/2, dim-half = t%2 (32 dims each).
// qkv layout: [B, T, 3*DMODEL]; Q at col 0, K at col DMODEL, V at 2*DMODEL,
// head h occupying 64 contiguous cols within each of Q/K/V.
// Output: [B, T, DMODEL] with head h at cols h*64.. (matches ref transpose).
// ---------------------------------------------------------------------------
__global__ __launch_bounds__(128)
void attn_kernel(const float* __restrict__ qkv, float* __restrict__ out)
{
    __shared__ float Ks[64][64];
    __shared__ float Vs[64][64];
    __shared__ float Ss[64][64];

    const int qt = blockIdx.x;      // 0..31
    const int h  = blockIdx.y;      // 0..15
    const int b  = blockIdx.z;      // 0..1

    const int t    = threadIdx.x;   // 0..127
    const int qi   = t >> 1;        // 0..63
    const int half = t & 1;         // 0 or 1
    const int qrow = qt * 64 + qi;

    const float* qptr = qkv + ((size_t)(b * SEQ + qrow)) * (3 * DMODEL)
                            + h * DHEAD + half * 32;
    float q[32];
#pragma unroll
    for (int d = 0; d < 32; d++) q[d] = qptr[d];

    float o[32];
#pragma unroll
    for (int d = 0; d < 32; d++) o[d] = 0.f;
    float m = -INFINITY, l = 0.f;

    for (int kt = 0; kt <= qt; kt++) {
        const float* kbase = qkv + ((size_t)(b * SEQ + kt * 64)) * (3 * DMODEL)
                                 + h * DHEAD + DMODEL;
        const float* vbase = kbase + DMODEL;
        // cooperative tile load: 1024 float4 per tensor, 8 per thread
#pragma unroll
        for (int i = 0; i < 8; i++) {
            int idx = t * 8 + i;          // 0..1023
            int r   = idx >> 4;
            int c4  = idx & 15;
            *(float4*)&Ks[r][c4 * 4] = ((const float4*)(kbase + (size_t)r * (3 * DMODEL)))[c4];
            *(float4*)&Vs[r][c4 * 4] = ((const float4*)(vbase + (size_t)r * (3 * DMODEL)))[c4];
        }
        __syncthreads();

        // scores
#pragma unroll 4
        for (int j = 0; j < 64; j++) {
            float s = 0.f;
#pragma unroll
            for (int d4 = 0; d4 < 8; d4++) {
                float4 kv = *(const float4*)&Ks[j][half * 32 + d4 * 4];
                s = fmaf(q[d4 * 4 + 0], kv.x, s);
                s = fmaf(q[d4 * 4 + 1], kv.y, s);
                s = fmaf(q[d4 * 4 + 2], kv.z, s);
                s = fmaf(q[d4 * 4 + 3], kv.w, s);
            }
            s += __shfl_xor_sync(0xffffffffu, s, 1);
            s *= 0.125f;                              // 1/sqrt(64)
            if (kt * 64 + j > qrow) s = -INFINITY;    // causal
            if (half == 0) Ss[qi][j] = s;
        }
        __syncthreads();

        // online softmax update
        float mt = m;
#pragma unroll 8
        for (int j = 0; j < 64; j++) mt = fmaxf(mt, Ss[qi][j]);
        float alpha = __expf(m - mt);
        m = mt;
        l *= alpha;
#pragma unroll
        for (int d = 0; d < 32; d++) o[d] *= alpha;

#pragma unroll 2
        for (int j = 0; j < 64; j++) {
            float p = __expf(Ss[qi][j] - mt);         // masked -> exp(-inf)=0
            l += p;
#pragma unroll
            for (int d4 = 0; d4 < 8; d4++) {
                float4 vv = *(const float4*)&Vs[j][half * 32 + d4 * 4];
                o[d4 * 4 + 0] = fmaf(p, vv.x, o[d4 * 4 + 0]);
                o[d4 * 4 + 1] = fmaf(p, vv.y, o[d4 * 4 + 1]);
                o[d4 * 4 + 2] = fmaf(p, vv.z, o[d4 * 4 + 2]);
                o[d4 * 4 + 3] = fmaf(p, vv.w, o[d4 * 4 + 3]);
            }
        }
        __syncthreads();
    }

    const float inv = 1.f / l;
    float* optr = out + ((size_t)(b * SEQ + qrow)) * DMODEL + h * DHEAD + half * 32;
#pragma unroll
    for (int d = 0; d < 32; d++) optr[d] = o[d] * inv;
}

// ---------------------------------------------------------------------------
// Fused residual add + LayerNorm: out = LN(A + B) * g + beta
// One block per row (1024 cols), 256 threads x float4.
// ---------------------------------------------------------------------------
__global__ __launch_bounds__(256)
void ln_kernel(const float* __restrict__ A, const float* __restrict__ B,
               const float* __restrict__ g, const float* __restrict__ be,
               float* __restrict__ out)
{
    const int row = blockIdx.x;
    const size_t off = (size_t)row * DMODEL;
    const int t = threadIdx.x;

    float4 a = ((const float4*)(A + off))[t];
    float4 b = ((const float4*)(B + off))[t];
    float x0 = a.x + b.x, x1 = a.y + b.y, x2 = a.z + b.z, x3 = a.w + b.w;

    float s  = x0 + x1 + x2 + x3;
    float s2 = x0 * x0 + x1 * x1 + x2 * x2 + x3 * x3;
#pragma unroll
    for (int o = 16; o; o >>= 1) {
        s  += __shfl_xor_sync(0xffffffffu, s, o);
        s2 += __shfl_xor_sync(0xffffffffu, s2, o);
    }
    __shared__ float ws[8], ws2[8];
    if ((t & 31) == 0) { ws[t >> 5] = s; ws2[t >> 5] = s2; }
    __syncthreads();
    s = 0.f; s2 = 0.f;
#pragma unroll
    for (int i = 0; i < 8; i++) { s += ws[i]; s2 += ws2[i]; }

    const float mean = s * (1.f / DMODEL);
    const float var  = s2 * (1.f / DMODEL) - mean * mean;
    const float rstd = rsqrtf(var + LN_EPS);

    float4 gg = ((const float4*)g)[t];
    float4 bb = ((const float4*)be)[t];
    float4 y;
    y.x = (x0 - mean) * rstd * gg.x + bb.x;
    y.y = (x1 - mean) * rstd * gg.y + bb.y;
    y.z = (x2 - mean) * rstd * gg.z + bb.z;
    y.w = (x3 - mean) * rstd * gg.w + bb.w;
    ((float4*)(out + off))[t] = y;
}

// ---------------------------------------------------------------------------
// Launcher
// Inputs (metadata order): X, W_qkv, b_qkv, W_o, b_o, W_1, b_1, W_2, b_2,
//                          ln1_g, ln1_b, ln2_g, ln2_b
// ---------------------------------------------------------------------------
extern "C" void kernel_launch(void* const* d_in, const int* in_sizes, int n_in,
                              void* d_out, int out_size)
{
    const float* X     = (const float*)d_in[0];
    const float* W_qkv = (const float*)d_in[1];
    const float* b_qkv = (const float*)d_in[2];
    const float* W_o   = (const float*)d_in[3];
    const float* b_o   = (const float*)d_in[4];
    const float* W_1   = (const float*)d_in[5];
    const float* b_1   = (const float*)d_in[6];
    const float* W_2   = (const float*)d_in[7];
    const float* b_2   = (const float*)d_in[8];
    const float* ln1g  = (const float*)d_in[9];
    const float* ln1b  = (const float*)d_in[10];
    const float* ln2g  = (const float*)d_in[11];
    const float* ln2b  = (const float*)d_in[12];
    float* out = (float*)d_out;

    float *qkv, *attn, *h1, *tmp, *ffn;
    cudaGetSymbolAddress((void**)&qkv,  g_qkv);
    cudaGetSymbolAddress((void**)&attn, g_attn);
    cudaGetSymbolAddress((void**)&h1,   g_h1);
    cudaGetSymbolAddress((void**)&tmp,  g_tmp);
    cudaGetSymbolAddress((void**)&ffn,  g_ffn);

    // 1) QKV projection: [4096,1024] @ [1024,3072]
    sgemm_kernel<<<dim3(3 * DMODEL / 128, ROWS / 128), 256>>>(
        X, W_qkv, b_qkv, qkv, ROWS, 3 * DMODEL, DMODEL, 0);

    // 2) causal flash attention
    attn_kernel<<<dim3(SEQ / 64, NHEADS, BATCH), 128>>>(qkv, attn);

    // 3) output projection -> tmp
    sgemm_kernel<<<dim3(DMODEL / 128, ROWS / 128), 256>>>(
        attn, W_o, b_o, tmp, ROWS, DMODEL, DMODEL, 0);

    // 4) H1 = LN(X + O)
    ln_kernel<<<ROWS, 256>>>(X, tmp, ln1g, ln1b, h1);

    // 5) FF1 + GELU: [4096,1024] @ [1024,4096]
    sgemm_kernel<<<dim3(DFF / 128, ROWS / 128), 256>>>(
        h1, W_1, b_1, ffn, ROWS, DFF, DMODEL, 1);

    // 6) FF2: [4096,4096] @ [4096,1024] -> tmp
    sgemm_kernel<<<dim3(DMODEL / 128, ROWS / 128), 256>>>(
        ffn, W_2, b_2, tmp, ROWS, DMODEL, DFF, 0);

    // 7) out = LN(H1 + H2)
    ln_kernel<<<ROWS, 256>>>(h1, tmp, ln2g, ln2b, out);
}

// round 2
// speedup vs baseline: 3.7043x; 3.7043x over previous
#include <cuda_runtime.h>
#include <cuda_bf16.h>
#include <math.h>

// ---------------------------------------------------------------------------
// Problem constants
// ---------------------------------------------------------------------------
#define BATCH   2
#define SEQ     2048
#define DMODEL  1024
#define DFF     4096
#define NHEADS  16
#define DHEAD   64
#define ROWS    (BATCH * SEQ)            // 4096
#define LN_EPS  1e-5f

// ---------------------------------------------------------------------------
// Scratch (no cudaMalloc allowed) — __device__ globals
// ---------------------------------------------------------------------------
__device__ float g_qkv [(size_t)ROWS * 3 * DMODEL];   // 50 MB
__device__ float g_attn[(size_t)ROWS * DMODEL];       // 16 MB
__device__ float g_h1  [(size_t)ROWS * DMODEL];       // 16 MB
__device__ float g_tmp [(size_t)ROWS * DMODEL];       // 16 MB
__device__ float g_ffn [(size_t)ROWS * DFF];          // 67 MB

// ---------------------------------------------------------------------------
// tf32 helpers
// ---------------------------------------------------------------------------
__device__ __forceinline__ unsigned f2tf(float x) {
    unsigned r;
    asm("cvt.rna.tf32.f32 %0, %1;" : "=r"(r) : "f"(x));
    return r;
}

__device__ __forceinline__ void mma_tf32(float c[4], const unsigned a[4],
                                         const unsigned b[2]) {
    asm volatile(
        "mma.sync.aligned.m16n8k8.row.col.f32.tf32.tf32.f32 "
        "{%0,%1,%2,%3},{%4,%5,%6,%7},{%8,%9},{%0,%1,%2,%3};"
        : "+f"(c[0]), "+f"(c[1]), "+f"(c[2]), "+f"(c[3])
        : "r"(a[0]), "r"(a[1]), "r"(a[2]), "r"(a[3]), "r"(b[0]), "r"(b[1]));
}

__device__ __forceinline__ float gelu_exact(float x) {
    return 0.5f * x * (1.f + erff(x * 0.70710678118654752f));
}

// ---------------------------------------------------------------------------
// tf32 tensor-core GEMM: C[M,N] = act(A[M,K] @ B[K,N] + bias[N])
// BM=BN=128, BK=32, 256 threads (8 warps, 2x4), warp tile 64x32.
// Requires M%128==0, N%128==0, K%32==0.
// ---------------------------------------------------------------------------
__global__ __launch_bounds__(256)
void tgemm_kernel(const float* __restrict__ A, const float* __restrict__ B,
                  const float* __restrict__ bias, float* __restrict__ C,
                  int M, int N, int K, int act)
{
    __shared__ unsigned As[128][36];   // [m][k], pad 4 -> conflict-free frags
    __shared__ unsigned Bs[32][132];   // [k][n], pad 4

    const int tid  = threadIdx.x;
    const int lane = tid & 31;
    const int warp = tid >> 5;
    const int wm   = warp >> 2;        // 0..1 (M)
    const int wn   = warp & 3;         // 0..3 (N)
    const int g    = lane >> 2;        // 0..7
    const int tg   = lane & 3;         // 0..3
    const int bx   = blockIdx.x, by = blockIdx.y;

    const float* Abase = A + (size_t)(by * 128) * K;
    const float* Bbase = B + bx * 128;

    float4 aR[4], bR[4];

    float c[4][4][4];
#pragma unroll
    for (int mi = 0; mi < 4; mi++)
#pragma unroll
        for (int ni = 0; ni < 4; ni++)
#pragma unroll
            for (int k = 0; k < 4; k++) c[mi][ni][k] = 0.f;

    const int KT = K / 32;

    // prefetch tile 0
#pragma unroll
    for (int i = 0; i < 4; i++) {
        int f = tid + 256 * i;
        aR[i] = *(const float4*)(Abase + (size_t)(f >> 3) * K + (f & 7) * 4);
        bR[i] = *(const float4*)(Bbase + (size_t)(f >> 5) * N + (f & 31) * 4);
    }

    for (int kt = 0; kt < KT; kt++) {
        // convert + store to smem
#pragma unroll
        for (int i = 0; i < 4; i++) {
            int f = tid + 256 * i;
            uint4 av;
            av.x = f2tf(aR[i].x); av.y = f2tf(aR[i].y);
            av.z = f2tf(aR[i].z); av.w = f2tf(aR[i].w);
            *(uint4*)&As[f >> 3][(f & 7) * 4] = av;
            uint4 bv;
            bv.x = f2tf(bR[i].x); bv.y = f2tf(bR[i].y);
            bv.z = f2tf(bR[i].z); bv.w = f2tf(bR[i].w);
            *(uint4*)&Bs[f >> 5][(f & 31) * 4] = bv;
        }
        __syncthreads();

        if (kt + 1 < KT) {
#pragma unroll
            for (int i = 0; i < 4; i++) {
                int f = tid + 256 * i;
                aR[i] = *(const float4*)(Abase + (size_t)(f >> 3) * K +
                                         (kt + 1) * 32 + (f & 7) * 4);
                bR[i] = *(const float4*)(Bbase +
                                         (size_t)((kt + 1) * 32 + (f >> 5)) * N +
                                         (f & 31) * 4);
            }
        }

#pragma unroll
        for (int ks = 0; ks < 4; ks++) {
            unsigned af[4][4], bf[4][2];
#pragma unroll
            for (int mi = 0; mi < 4; mi++) {
                int r = wm * 64 + mi * 16 + g;
                af[mi][0] = As[r][ks * 8 + tg];
                af[mi][1] = As[r + 8][ks * 8 + tg];
                af[mi][2] = As[r][ks * 8 + tg + 4];
                af[mi][3] = As[r + 8][ks * 8 + tg + 4];
            }
#pragma unroll
            for (int ni = 0; ni < 4; ni++) {
                int col = wn * 32 + ni * 8 + g;
                bf[ni][0] = Bs[ks * 8 + tg][col];
                bf[ni][1] = Bs[ks * 8 + tg + 4][col];
            }
#pragma unroll
            for (int mi = 0; mi < 4; mi++)
#pragma unroll
                for (int ni = 0; ni < 4; ni++)
                    mma_tf32(c[mi][ni], af[mi], bf[ni]);
        }
        __syncthreads();
    }

    // epilogue: bias (+ GELU), fragment c maps to rows (g, g+8), cols (2tg, 2tg+1)
#pragma unroll
    for (int mi = 0; mi < 4; mi++) {
        int row = by * 128 + wm * 64 + mi * 16 + g;
#pragma unroll
        for (int ni = 0; ni < 4; ni++) {
            int col = bx * 128 + wn * 32 + ni * 8 + tg * 2;
            float b0 = bias[col], b1 = bias[col + 1];
            float v00 = c[mi][ni][0] + b0, v01 = c[mi][ni][1] + b1;
            float v10 = c[mi][ni][2] + b0, v11 = c[mi][ni][3] + b1;
            if (act == 1) {
                v00 = gelu_exact(v00); v01 = gelu_exact(v01);
                v10 = gelu_exact(v10); v11 = gelu_exact(v11);
            }
            *(float2*)&C[(size_t)row * N + col]       = make_float2(v00, v01);
            *(float2*)&C[(size_t)(row + 8) * N + col] = make_float2(v10, v11);
        }
    }
}

// ---------------------------------------------------------------------------
// Flash attention with tf32 tensor cores.
// One block = 64 queries x 1 head x 1 batch; 128 threads = 4 warps.
// Warp w owns queries [w*16, w*16+16). S and PV both via m16n8k8 tf32 mma.
// Online softmax kept per-query in smem (m_s, l_s, alpha_s).
// Dynamic smem: Qs,Ks,Vs (tf32) + Ss (fp32 scores / tf32 P), 64x68 each.
// ---------------------------------------------------------------------------
#define ATT_TILE_BYTES (64 * 68 * 4)
#define ATT_SMEM (4 * ATT_TILE_BYTES)

__global__ __launch_bounds__(128)
void attn_mma_kernel(const float* __restrict__ qkv, float* __restrict__ out)
{
    extern __shared__ char smraw[];
    unsigned (*Qs)[68] = (unsigned(*)[68])(smraw);
    unsigned (*Ks)[68] = (unsigned(*)[68])(smraw + ATT_TILE_BYTES);
    unsigned (*Vs)[68] = (unsigned(*)[68])(smraw + 2 * ATT_TILE_BYTES);
    float    (*Ss)[68] = (float(*)[68])  (smraw + 3 * ATT_TILE_BYTES);
    __shared__ float m_s[64], l_s[64], alpha_s[64];

    const int qt = blockIdx.x, h = blockIdx.y, b = blockIdx.z;
    const int t = threadIdx.x, lane = t & 31, w = t >> 5;
    const int g = lane >> 2, tg = lane & 3;

    // Load Q tile (64x64) once, as tf32
    const float* qbase = qkv + (size_t)(b * SEQ + qt * 64) * (3 * DMODEL) + h * DHEAD;
#pragma unroll
    for (int i = 0; i < 8; i++) {
        int f = t + 128 * i;
        int r = f >> 4, c4 = f & 15;
        float4 v = *(const float4*)(qbase + (size_t)r * (3 * DMODEL) + c4 * 4);
        uint4 u;
        u.x = f2tf(v.x); u.y = f2tf(v.y); u.z = f2tf(v.z); u.w = f2tf(v.w);
        *(uint4*)&Qs[r][c4 * 4] = u;
    }
    if (t < 64) { m_s[t] = -INFINITY; l_s[t] = 0.f; }

    float co[8][4];
#pragma unroll
    for (int ni = 0; ni < 8; ni++)
#pragma unroll
        for (int k = 0; k < 4; k++) co[ni][k] = 0.f;

    for (int kt = 0; kt <= qt; kt++) {
        const float* kbase = qkv + (size_t)(b * SEQ + kt * 64) * (3 * DMODEL)
                           + DMODEL + h * DHEAD;
        const float* vbase = kbase + DMODEL;
#pragma unroll
        for (int i = 0; i < 8; i++) {
            int f = t + 128 * i;
            int r = f >> 4, c4 = f & 15;
            float4 kv = *(const float4*)(kbase + (size_t)r * (3 * DMODEL) + c4 * 4);
            float4 vv = *(const float4*)(vbase + (size_t)r * (3 * DMODEL) + c4 * 4);
            uint4 ku, vu;
            ku.x = f2tf(kv.x); ku.y = f2tf(kv.y); ku.z = f2tf(kv.z); ku.w = f2tf(kv.w);
            vu.x = f2tf(vv.x); vu.y = f2tf(vv.y); vu.z = f2tf(vv.z); vu.w = f2tf(vv.w);
            *(uint4*)&Ks[r][c4 * 4] = ku;
            *(uint4*)&Vs[r][c4 * 4] = vu;
        }
        __syncthreads();   // also orders Q store / m_s init on first iter

        // ---- S = Q @ K^T (warp: 16 queries x 64 keys, k-dim 64) ----
        float cs[8][4];
#pragma unroll
        for (int ni = 0; ni < 8; ni++)
#pragma unroll
            for (int k = 0; k < 4; k++) cs[ni][k] = 0.f;

#pragma unroll
        for (int ks = 0; ks < 8; ks++) {
            unsigned af[4];
            int r = w * 16 + g;
            af[0] = Qs[r][ks * 8 + tg];
            af[1] = Qs[r + 8][ks * 8 + tg];
            af[2] = Qs[r][ks * 8 + tg + 4];
            af[3] = Qs[r + 8][ks * 8 + tg + 4];
#pragma unroll
            for (int ni = 0; ni < 8; ni++) {
                unsigned bf[2];
                bf[0] = Ks[ni * 8 + g][ks * 8 + tg];
                bf[1] = Ks[ni * 8 + g][ks * 8 + tg + 4];
                mma_tf32(cs[ni], af, bf);
            }
        }

        // scale + causal mask + write scores to smem
        {
            int qr = qt * 64 + w * 16 + g;
            bool diag = (kt == qt);
#pragma unroll
            for (int ni = 0; ni < 8; ni++) {
                int col = ni * 8 + tg * 2;
                float s00 = cs[ni][0] * 0.125f;
                float s01 = cs[ni][1] * 0.125f;
                float s10 = cs[ni][2] * 0.125f;
                float s11 = cs[ni][3] * 0.125f;
                if (diag) {
                    int kg = kt * 64 + col;
                    if (kg     > qr)     s00 = -INFINITY;
                    if (kg + 1 > qr)     s01 = -INFINITY;
                    if (kg     > qr + 8) s10 = -INFINITY;
                    if (kg + 1 > qr + 8) s11 = -INFINITY;
                }
                Ss[w * 16 + g][col]     = s00;
                Ss[w * 16 + g][col + 1] = s01;
                Ss[w * 16 + g + 8][col]     = s10;
                Ss[w * 16 + g + 8][col + 1] = s11;
            }
        }
        __syncthreads();

        // ---- online softmax: 2 threads per query ----
        {
            int qi = t >> 1, hf = t & 1;
            float sv[32];
            float mloc = -INFINITY;
#pragma unroll
            for (int j = 0; j < 32; j++) {
                sv[j] = Ss[qi][hf * 32 + j];
                mloc = fmaxf(mloc, sv[j]);
            }
            mloc = fmaxf(mloc, __shfl_xor_sync(0xffffffffu, mloc, 1));
            float mold = m_s[qi];
            float mt = fmaxf(mold, mloc);
            float psum = 0.f;
#pragma unroll
            for (int j = 0; j < 32; j++) {
                float p = __expf(sv[j] - mt);      // -inf -> 0
                psum += p;
                Ss[qi][hf * 32 + j] = __uint_as_float(f2tf(p));
            }
            psum += __shfl_xor_sync(0xffffffffu, psum, 1);
            if (hf == 0) {
                float alpha = __expf(mold - mt);   // first tile: exp(-inf)=0
                m_s[qi] = mt;
                l_s[qi] = l_s[qi] * alpha + psum;
                alpha_s[qi] = alpha;
            }
        }
        __syncthreads();

        // ---- O = O*alpha + P @ V ----
        {
            float alo = alpha_s[w * 16 + g];
            float ahi = alpha_s[w * 16 + g + 8];
#pragma unroll
            for (int ni = 0; ni < 8; ni++) {
                co[ni][0] *= alo; co[ni][1] *= alo;
                co[ni][2] *= ahi; co[ni][3] *= ahi;
            }
#pragma unroll
            for (int ks = 0; ks < 8; ks++) {
                unsigned af[4];
                int r = w * 16 + g;
                af[0] = __float_as_uint(Ss[r][ks * 8 + tg]);
                af[1] = __float_as_uint(Ss[r + 8][ks * 8 + tg]);
                af[2] = __float_as_uint(Ss[r][ks * 8 + tg + 4]);
                af[3] = __float_as_uint(Ss[r + 8][ks * 8 + tg + 4]);
#pragma unroll
                for (int ni = 0; ni < 8; ni++) {
                    unsigned bf[2];
                    bf[0] = Vs[ks * 8 + tg][ni * 8 + g];
                    bf[1] = Vs[ks * 8 + tg + 4][ni * 8 + g];
                    mma_tf32(co[ni], af, bf);
                }
            }
        }
        __syncthreads();   // protect Ks/Vs/Ss before next tile
    }

    // final normalize + store (out head h at cols h*64)
    float llo = 1.f / l_s[w * 16 + g];
    float lhi = 1.f / l_s[w * 16 + g + 8];
    int row0 = b * SEQ + qt * 64 + w * 16 + g;
    float* ob = out + (size_t)row0 * DMODEL + h * DHEAD;
#pragma unroll
    for (int ni = 0; ni < 8; ni++) {
        int col = ni * 8 + tg * 2;
        *(float2*)&ob[col] = make_float2(co[ni][0] * llo, co[ni][1] * llo);
        *(float2*)&ob[(size_t)8 * DMODEL + col] =
            make_float2(co[ni][2] * lhi, co[ni][3] * lhi);
    }
}

// ---------------------------------------------------------------------------
// Fused residual add + LayerNorm: out = LN(A + B) * g + beta
// ---------------------------------------------------------------------------
__global__ __launch_bounds__(256)
void ln_kernel(const float* __restrict__ A, const float* __restrict__ B,
               const float* __restrict__ g, const float* __restrict__ be,
               float* __restrict__ out)
{
    const int row = blockIdx.x;
    const size_t off = (size_t)row * DMODEL;
    const int t = threadIdx.x;

    float4 a = ((const float4*)(A + off))[t];
    float4 b = ((const float4*)(B + off))[t];
    float x0 = a.x + b.x, x1 = a.y + b.y, x2 = a.z + b.z, x3 = a.w + b.w;

    float s  = x0 + x1 + x2 + x3;
    float s2 = x0 * x0 + x1 * x1 + x2 * x2 + x3 * x3;
#pragma unroll
    for (int o = 16; o; o >>= 1) {
        s  += __shfl_xor_sync(0xffffffffu, s, o);
        s2 += __shfl_xor_sync(0xffffffffu, s2, o);
    }
    __shared__ float ws[8], ws2[8];
    if ((t & 31) == 0) { ws[t >> 5] = s; ws2[t >> 5] = s2; }
    __syncthreads();
    s = 0.f; s2 = 0.f;
#pragma unroll
    for (int i = 0; i < 8; i++) { s += ws[i]; s2 += ws2[i]; }

    const float mean = s * (1.f / DMODEL);
    const float var  = s2 * (1.f / DMODEL) - mean * mean;
    const float rstd = rsqrtf(var + LN_EPS);

    float4 gg = ((const float4*)g)[t];
    float4 bb = ((const float4*)be)[t];
    float4 y;
    y.x = (x0 - mean) * rstd * gg.x + bb.x;
    y.y = (x1 - mean) * rstd * gg.y + bb.y;
    y.z = (x2 - mean) * rstd * gg.z + bb.z;
    y.w = (x3 - mean) * rstd * gg.w + bb.w;
    ((float4*)(out + off))[t] = y;
}

// ---------------------------------------------------------------------------
// Launcher
// ---------------------------------------------------------------------------
extern "C" void kernel_launch(void* const* d_in, const int* in_sizes, int n_in,
                              void* d_out, int out_size)
{
    const float* X     = (const float*)d_in[0];
    const float* W_qkv = (const float*)d_in[1];
    const float* b_qkv = (const float*)d_in[2];
    const float* W_o   = (const float*)d_in[3];
    const float* b_o   = (const float*)d_in[4];
    const float* W_1   = (const float*)d_in[5];
    const float* b_1   = (const float*)d_in[6];
    const float* W_2   = (const float*)d_in[7];
    const float* b_2   = (const float*)d_in[8];
    const float* ln1g  = (const float*)d_in[9];
    const float* ln1b  = (const float*)d_in[10];
    const float* ln2g  = (const float*)d_in[11];
    const float* ln2b  = (const float*)d_in[12];
    float* out = (float*)d_out;

    float *qkv, *attn, *h1, *tmp, *ffn;
    cudaGetSymbolAddress((void**)&qkv,  g_qkv);
    cudaGetSymbolAddress((void**)&attn, g_attn);
    cudaGetSymbolAddress((void**)&h1,   g_h1);
    cudaGetSymbolAddress((void**)&tmp,  g_tmp);
    cudaGetSymbolAddress((void**)&ffn,  g_ffn);

    cudaFuncSetAttribute(attn_mma_kernel,
                         cudaFuncAttributeMaxDynamicSharedMemorySize, ATT_SMEM);

    // 1) QKV projection: [4096,1024] @ [1024,3072]
    tgemm_kernel<<<dim3(3 * DMODEL / 128, ROWS / 128), 256>>>(
        X, W_qkv, b_qkv, qkv, ROWS, 3 * DMODEL, DMODEL, 0);

    // 2) causal flash attention (tf32 tensor cores)
    attn_mma_kernel<<<dim3(SEQ / 64, NHEADS, BATCH), 128, ATT_SMEM>>>(qkv, attn);

    // 3) output projection -> tmp
    tgemm_kernel<<<dim3(DMODEL / 128, ROWS / 128), 256>>>(
        attn, W_o, b_o, tmp, ROWS, DMODEL, DMODEL, 0);

    // 4) H1 = LN(X + O)
    ln_kernel<<<ROWS, 256>>>(X, tmp, ln1g, ln1b, h1);

    // 5) FF1 + GELU: [4096,1024] @ [1024,4096]
    tgemm_kernel<<<dim3(DFF / 128, ROWS / 128), 256>>>(
        h1, W_1, b_1, ffn, ROWS, DFF, DMODEL, 1);

    // 6) FF2: [4096,4096] @ [4096,1024] -> tmp
    tgemm_kernel<<<dim3(DMODEL / 128, ROWS / 128), 256>>>(
        ffn, W_2, b_2, tmp, ROWS, DMODEL, DFF, 0);

    // 7) out = LN(H1 + H2)
    ln_kernel<<<ROWS, 256>>>(h1, tmp, ln2g, ln2b, out);
}

// round 4
// speedup vs baseline: 5.9671x; 1.6109x over previous
#include <cuda_runtime.h>
#include <cuda_fp16.h>
#include <math.h>
#include <stdint.h>

// ---------------------------------------------------------------------------
// Problem constants
// ---------------------------------------------------------------------------
#define BATCH   2
#define SEQ     2048
#define DMODEL  1024
#define DFF     4096
#define NHEADS  16
#define DHEAD   64
#define ROWS    (BATCH * SEQ)            // 4096
#define LN_EPS  1e-5f

// ---------------------------------------------------------------------------
// Scratch — __device__ globals (no cudaMalloc allowed)
// ---------------------------------------------------------------------------
__device__ __half g_qkv [(size_t)ROWS * 3 * DMODEL];  // 25 MB (fp16)
__device__ __half g_attn[(size_t)ROWS * DMODEL];      //  8 MB (fp16)
__device__ __half g_ffn [(size_t)ROWS * DFF];         // 33 MB (fp16)
__device__ float  g_h1  [(size_t)ROWS * DMODEL];      // 16 MB
__device__ float  g_tmp [(size_t)ROWS * DMODEL];      // 16 MB
__device__ __half g_wt  [(size_t)12288 * 1024];       // 25 MB transposed fp16 weights

// offsets (elements) inside g_wt
#define WT_QKV 0
#define WT_O   (3072 * 1024)
#define WT_1   (WT_O + 1024 * 1024)
#define WT_2   (WT_1 + 4096 * 1024)

// ---------------------------------------------------------------------------
// helpers
// ---------------------------------------------------------------------------
__device__ __forceinline__ unsigned pack2(float x, float y) {
    __half2 h = __floats2half2_rn(x, y);
    return *reinterpret_cast<unsigned*>(&h);
}
__device__ __forceinline__ uint4 pack8(const float4& a, const float4& b) {
    uint4 u;
    u.x = pack2(a.x, a.y); u.y = pack2(a.z, a.w);
    u.z = pack2(b.x, b.y); u.w = pack2(b.z, b.w);
    return u;
}

__device__ __forceinline__ void mma_f16(float c[4], const unsigned a[4],
                                        const unsigned b[2]) {
    asm volatile(
        "mma.sync.aligned.m16n8k16.row.col.f32.f16.f16.f32 "
        "{%0,%1,%2,%3},{%4,%5,%6,%7},{%8,%9},{%0,%1,%2,%3};"
        : "+f"(c[0]), "+f"(c[1]), "+f"(c[2]), "+f"(c[3])
        : "r"(a[0]), "r"(a[1]), "r"(a[2]), "r"(a[3]), "r"(b[0]), "r"(b[1]));
}

#define U32(p) (*reinterpret_cast<const unsigned*>(p))

__device__ __forceinline__ float gelu_exact(float x) {
    return 0.5f * x * (1.f + erff(x * 0.70710678118654752f));
}

// ---------------------------------------------------------------------------
// Weight transpose + fp16 convert: out[C,R] = (half)in[R,C]^T
// ---------------------------------------------------------------------------
__global__ __launch_bounds__(256)
void transpose_h(const float* __restrict__ in, __half* __restrict__ out,
                 int R, int C)
{
    __shared__ float tile[32][33];
    const int c0 = blockIdx.x * 32, r0 = blockIdx.y * 32;
    const int tx = threadIdx.x & 31, ty = threadIdx.x >> 5;   // 32 x 8
#pragma unroll
    for (int i = ty; i < 32; i += 8)
        tile[i][tx] = in[(size_t)(r0 + i) * C + c0 + tx];
    __syncthreads();
#pragma unroll
    for (int i = ty; i < 32; i += 8)
        out[(size_t)(c0 + i) * R + r0 + tx] = __float2half(tile[tx][i]);
}

// ---------------------------------------------------------------------------
// fp16 tensor-core GEMM: C[M,N] = act(A[M,K] @ Bt[N,K]^T + bias[N])
// A fp32 or fp16 (AH); C fp32 or fp16 (OH). Bt fp16 [N,K] row-major.
// BM=BN=128, BK=32 halfs, 256 threads (8 warps 2x4), warp tile 64x32.
// m16n8k16 mma; smem padded to 40 halfs/row (conflict-free frag loads).
// ---------------------------------------------------------------------------
template<bool AH, bool OH, int ACT>
__global__ __launch_bounds__(256)
void hgemm(const void* __restrict__ Av, const __half* __restrict__ Bt,
           const float* __restrict__ bias, void* __restrict__ Cv,
           int M, int N, int K)
{
    __shared__ __half As[128][40];
    __shared__ __half Bs[128][40];

    const int tid = threadIdx.x, lane = tid & 31, warp = tid >> 5;
    const int wm = warp >> 2, wn = warp & 3;
    const int g = lane >> 2, tg = lane & 3;
    const int bx = blockIdx.x, by = blockIdx.y;

    const float*  Af = (const float*)Av;
    const __half* Ah = (const __half*)Av;
    const __half* Bbase = Bt + (size_t)(bx * 128) * K;

    float c[4][4][4];
#pragma unroll
    for (int mi = 0; mi < 4; mi++)
#pragma unroll
        for (int ni = 0; ni < 4; ni++)
#pragma unroll
            for (int k = 0; k < 4; k++) c[mi][ni][k] = 0.f;

    const int KT = K / 32;
    uint4 aR[2], bR[2];

    // prefetch kt = 0
#pragma unroll
    for (int p = 0; p < 2; p++) {
        int f = tid + 256 * p;
        int r = f >> 2, kc = (f & 3) * 8;
        if (AH) {
            aR[p] = *(const uint4*)(Ah + (size_t)(by * 128 + r) * K + kc);
        } else {
            const float* ap = Af + (size_t)(by * 128 + r) * K + kc;
            aR[p] = pack8(*(const float4*)ap, *(const float4*)(ap + 4));
        }
        bR[p] = *(const uint4*)(Bbase + (size_t)r * K + kc);
    }

    for (int kt = 0; kt < KT; kt++) {
        // store current chunk
#pragma unroll
        for (int p = 0; p < 2; p++) {
            int f = tid + 256 * p;
            int r = f >> 2, kc = (f & 3) * 8;
            *(uint4*)&As[r][kc] = aR[p];
            *(uint4*)&Bs[r][kc] = bR[p];
        }
        __syncthreads();

        // prefetch next chunk
        if (kt + 1 < KT) {
            const int ko = (kt + 1) * 32;
#pragma unroll
            for (int p = 0; p < 2; p++) {
                int f = tid + 256 * p;
                int r = f >> 2, kc = (f & 3) * 8;
                if (AH) {
                    aR[p] = *(const uint4*)(Ah + (size_t)(by * 128 + r) * K + ko + kc);
                } else {
                    const float* ap = Af + (size_t)(by * 128 + r) * K + ko + kc;
                    aR[p] = pack8(*(const float4*)ap, *(const float4*)(ap + 4));
                }
                bR[p] = *(const uint4*)(Bbase + (size_t)r * K + ko + kc);
            }
        }

        // compute: 2 k16 steps
#pragma unroll
        for (int ks = 0; ks < 2; ks++) {
            unsigned af[4][4], bf[4][2];
#pragma unroll
            for (int mi = 0; mi < 4; mi++) {
                int r = wm * 64 + mi * 16 + g;
                af[mi][0] = U32(&As[r][ks * 16 + 2 * tg]);
                af[mi][1] = U32(&As[r + 8][ks * 16 + 2 * tg]);
                af[mi][2] = U32(&As[r][ks * 16 + 2 * tg + 8]);
                af[mi][3] = U32(&As[r + 8][ks * 16 + 2 * tg + 8]);
            }
#pragma unroll
            for (int ni = 0; ni < 4; ni++) {
                int col = wn * 32 + ni * 8 + g;
                bf[ni][0] = U32(&Bs[col][ks * 16 + 2 * tg]);
                bf[ni][1] = U32(&Bs[col][ks * 16 + 2 * tg + 8]);
            }
#pragma unroll
            for (int mi = 0; mi < 4; mi++)
#pragma unroll
                for (int ni = 0; ni < 4; ni++)
                    mma_f16(c[mi][ni], af[mi], bf[ni]);
        }
        __syncthreads();
    }

    // epilogue
#pragma unroll
    for (int mi = 0; mi < 4; mi++) {
        int row = by * 128 + wm * 64 + mi * 16 + g;
#pragma unroll
        for (int ni = 0; ni < 4; ni++) {
            int col = bx * 128 + wn * 32 + ni * 8 + tg * 2;
            float b0 = bias[col], b1 = bias[col + 1];
            float v00 = c[mi][ni][0] + b0, v01 = c[mi][ni][1] + b1;
            float v10 = c[mi][ni][2] + b0, v11 = c[mi][ni][3] + b1;
            if (ACT == 1) {
                v00 = gelu_exact(v00); v01 = gelu_exact(v01);
                v10 = gelu_exact(v10); v11 = gelu_exact(v11);
            }
            if (OH) {
                __half* C = (__half*)Cv;
                *(__half2*)&C[(size_t)row * N + col] = __floats2half2_rn(v00, v01);
                *(__half2*)&C[(size_t)(row + 8) * N + col] = __floats2half2_rn(v10, v11);
            } else {
                float* C = (float*)Cv;
                *(float2*)&C[(size_t)row * N + col]       = make_float2(v00, v01);
                *(float2*)&C[(size_t)(row + 8) * N + col] = make_float2(v10, v11);
            }
        }
    }
}

// ---------------------------------------------------------------------------
// Flash attention, fp16 operands, fp32 softmax/accum.
// One block = 64 queries x 1 head x 1 batch; 128 threads = 4 warps.
// qkv is fp16 [B,T,3*DMODEL]. Output attn fp16 [B,T,DMODEL].
// ---------------------------------------------------------------------------
#define OFF_Q  0
#define OFF_K  9216
#define OFF_VT 18432
#define OFF_S  27648
#define OFF_P  45056
#define ATT_SMEM (45056 + 9216)

__global__ __launch_bounds__(128)
void attn_h_kernel(const __half* __restrict__ qkv, __half* __restrict__ out)
{
    extern __shared__ char sm[];
    __half (*Qs)[72] = (__half(*)[72])(sm + OFF_Q);
    __half (*Ks)[72] = (__half(*)[72])(sm + OFF_K);
    __half (*Vt)[72] = (__half(*)[72])(sm + OFF_VT);   // [dim][key]
    float  (*Ss)[68] = (float(*)[68]) (sm + OFF_S);
    __half (*Ps)[72] = (__half(*)[72])(sm + OFF_P);
    __shared__ float m_s[64], l_s[64], alpha_s[64];

    const int qt = blockIdx.x, h = blockIdx.y, b = blockIdx.z;
    const int t = threadIdx.x, lane = t & 31, w = t >> 5;
    const int g = lane >> 2, tg = lane & 3;

    // Q tile: 64 x 64 halfs
    const __half* qbase = qkv + (size_t)(b * SEQ + qt * 64) * (3 * DMODEL) + h * DHEAD;
#pragma unroll
    for (int i = 0; i < 4; i++) {
        int f = t + 128 * i;
        int r = f >> 3, c8 = f & 7;
        uint4 v = *(const uint4*)(qbase + (size_t)r * (3 * DMODEL) + c8 * 8);
        *(uint4*)&Qs[r][c8 * 8] = v;
    }
    if (t < 64) { m_s[t] = -INFINITY; l_s[t] = 0.f; }

    float co[8][4];
#pragma unroll
    for (int ni = 0; ni < 8; ni++)
#pragma unroll
        for (int k = 0; k < 4; k++) co[ni][k] = 0.f;

    for (int kt = 0; kt <= qt; kt++) {
        const __half* kbase = qkv + (size_t)(b * SEQ + kt * 64) * (3 * DMODEL)
                            + DMODEL + h * DHEAD;
        const __half* vbase = kbase + DMODEL;
#pragma unroll
        for (int i = 0; i < 4; i++) {
            int f = t + 128 * i;
            int r = f >> 3, c8 = f & 7;
            uint4 kv = *(const uint4*)(kbase + (size_t)r * (3 * DMODEL) + c8 * 8);
            *(uint4*)&Ks[r][c8 * 8] = kv;
            // V transposed: Vt[dim][key]
            uint4 vv = *(const uint4*)(vbase + (size_t)r * (3 * DMODEL) + c8 * 8);
            const __half* vh = (const __half*)&vv;
#pragma unroll
            for (int j = 0; j < 8; j++) Vt[c8 * 8 + j][r] = vh[j];
        }
        __syncthreads();

        // ---- S = Q @ K^T ----
        float cs[8][4];
#pragma unroll
        for (int ni = 0; ni < 8; ni++)
#pragma unroll
            for (int k = 0; k < 4; k++) cs[ni][k] = 0.f;

#pragma unroll
        for (int ks = 0; ks < 4; ks++) {
            unsigned af[4];
            int r = w * 16 + g;
            af[0] = U32(&Qs[r][ks * 16 + 2 * tg]);
            af[1] = U32(&Qs[r + 8][ks * 16 + 2 * tg]);
            af[2] = U32(&Qs[r][ks * 16 + 2 * tg + 8]);
            af[3] = U32(&Qs[r + 8][ks * 16 + 2 * tg + 8]);
#pragma unroll
            for (int ni = 0; ni < 8; ni++) {
                unsigned bf[2];
                bf[0] = U32(&Ks[ni * 8 + g][ks * 16 + 2 * tg]);
                bf[1] = U32(&Ks[ni * 8 + g][ks * 16 + 2 * tg + 8]);
                mma_f16(cs[ni], af, bf);
            }
        }

        // scale + causal mask -> Ss (fp32)
        {
            int qr = qt * 64 + w * 16 + g;
            bool diag = (kt == qt);
#pragma unroll
            for (int ni = 0; ni < 8; ni++) {
                int col = ni * 8 + tg * 2;
                float s00 = cs[ni][0] * 0.125f;
                float s01 = cs[ni][1] * 0.125f;
                float s10 = cs[ni][2] * 0.125f;
                float s11 = cs[ni][3] * 0.125f;
                if (diag) {
                    int kg = kt * 64 + col;
                    if (kg     > qr)     s00 = -INFINITY;
                    if (kg + 1 > qr)     s01 = -INFINITY;
                    if (kg     > qr + 8) s10 = -INFINITY;
                    if (kg + 1 > qr + 8) s11 = -INFINITY;
                }
                Ss[w * 16 + g][col]         = s00;
                Ss[w * 16 + g][col + 1]     = s01;
                Ss[w * 16 + g + 8][col]     = s10;
                Ss[w * 16 + g + 8][col + 1] = s11;
            }
        }
        __syncthreads();

        // ---- online softmax (2 threads / query) -> Ps (fp16) ----
        {
            int qi = t >> 1, hf = t & 1;
            float sv[32];
            float mloc = -INFINITY;
#pragma unroll
            for (int j = 0; j < 32; j++) {
                sv[j] = Ss[qi][hf * 32 + j];
                mloc = fmaxf(mloc, sv[j]);
            }
            mloc = fmaxf(mloc, __shfl_xor_sync(0xffffffffu, mloc, 1));
            float mold = m_s[qi];
            float mt = fmaxf(mold, mloc);
            float psum = 0.f;
#pragma unroll
            for (int j = 0; j < 32; j += 2) {
                float p0 = __expf(sv[j] - mt);
                float p1 = __expf(sv[j + 1] - mt);
                psum += p0 + p1;
                *(__half2*)&Ps[qi][hf * 32 + j] = __floats2half2_rn(p0, p1);
            }
            psum += __shfl_xor_sync(0xffffffffu, psum, 1);
            if (hf == 0) {
                float alpha = __expf(mold - mt);
                m_s[qi] = mt;
                l_s[qi] = l_s[qi] * alpha + psum;
                alpha_s[qi] = alpha;
            }
        }
        __syncthreads();

        // ---- O = O*alpha + P @ V ----
        {
            float alo = alpha_s[w * 16 + g];
            float ahi = alpha_s[w * 16 + g + 8];
#pragma unroll
            for (int ni = 0; ni < 8; ni++) {
                co[ni][0] *= alo; co[ni][1] *= alo;
                co[ni][2] *= ahi; co[ni][3] *= ahi;
            }
#pragma unroll
            for (int ks = 0; ks < 4; ks++) {
                unsigned af[4];
                int r = w * 16 + g;
                af[0] = U32(&Ps[r][ks * 16 + 2 * tg]);
                af[1] = U32(&Ps[r + 8][ks * 16 + 2 * tg]);
                af[2] = U32(&Ps[r][ks * 16 + 2 * tg + 8]);
                af[3] = U32(&Ps[r + 8][ks * 16 + 2 * tg + 8]);
#pragma unroll
                for (int ni = 0; ni < 8; ni++) {
                    unsigned bf[2];
                    bf[0] = U32(&Vt[ni * 8 + g][ks * 16 + 2 * tg]);
                    bf[1] = U32(&Vt[ni * 8 + g][ks * 16 + 2 * tg + 8]);
                    mma_f16(co[ni], af, bf);
                }
            }
        }
        __syncthreads();
    }

    // normalize + store fp16
    float llo = 1.f / l_s[w * 16 + g];
    float lhi = 1.f / l_s[w * 16 + g + 8];
    int row0 = b * SEQ + qt * 64 + w * 16 + g;
    __half* ob = out + (size_t)row0 * DMODEL + h * DHEAD;
#pragma unroll
    for (int ni = 0; ni < 8; ni++) {
        int col = ni * 8 + tg * 2;
        *(__half2*)&ob[col] =
            __floats2half2_rn(co[ni][0] * llo, co[ni][1] * llo);
        *(__half2*)&ob[(size_t)8 * DMODEL + col] =
            __floats2half2_rn(co[ni][2] * lhi, co[ni][3] * lhi);
    }
}

// ---------------------------------------------------------------------------
// Fused residual add + LayerNorm (fp32)
// ---------------------------------------------------------------------------
__global__ __launch_bounds__(256)
void ln_kernel(const float* __restrict__ A, const float* __restrict__ B,
               const float* __restrict__ g, const float* __restrict__ be,
               float* __restrict__ out)
{
    const int row = blockIdx.x;
    const size_t off = (size_t)row * DMODEL;
    const int t = threadIdx.x;

    float4 a = ((const float4*)(A + off))[t];
    float4 b = ((const float4*)(B + off))[t];
    float x0 = a.x + b.x, x1 = a.y + b.y, x2 = a.z + b.z, x3 = a.w + b.w;

    float s  = x0 + x1 + x2 + x3;
    float s2 = x0 * x0 + x1 * x1 + x2 * x2 + x3 * x3;
#pragma unroll
    for (int o = 16; o; o >>= 1) {
        s  += __shfl_xor_sync(0xffffffffu, s, o);
        s2 += __shfl_xor_sync(0xffffffffu, s2, o);
    }
    __shared__ float ws[8], ws2[8];
    if ((t & 31) == 0) { ws[t >> 5] = s; ws2[t >> 5] = s2; }
    __syncthreads();
    s = 0.f; s2 = 0.f;
#pragma unroll
    for (int i = 0; i < 8; i++) { s += ws[i]; s2 += ws2[i]; }

    const float mean = s * (1.f / DMODEL);
    const float var  = s2 * (1.f / DMODEL) - mean * mean;
    const float rstd = rsqrtf(var + LN_EPS);

    float4 gg = ((const float4*)g)[t];
    float4 bb = ((const float4*)be)[t];
    float4 y;
    y.x = (x0 - mean) * rstd * gg.x + bb.x;
    y.y = (x1 - mean) * rstd * gg.y + bb.y;
    y.z = (x2 - mean) * rstd * gg.z + bb.z;
    y.w = (x3 - mean) * rstd * gg.w + bb.w;
    ((float4*)(out + off))[t] = y;
}

// ---------------------------------------------------------------------------
// Launcher
// ---------------------------------------------------------------------------
extern "C" void kernel_launch(void* const* d_in, const int* in_sizes, int n_in,
                              void* d_out, int out_size)
{
    const float* X     = (const float*)d_in[0];
    const float* W_qkv = (const float*)d_in[1];
    const float* b_qkv = (const float*)d_in[2];
    const float* W_o   = (const float*)d_in[3];
    const float* b_o   = (const float*)d_in[4];
    const float* W_1   = (const float*)d_in[5];
    const float* b_1   = (const float*)d_in[6];
    const float* W_2   = (const float*)d_in[7];
    const float* b_2   = (const float*)d_in[8];
    const float* ln1g  = (const float*)d_in[9];
    const float* ln1b  = (const float*)d_in[10];
    const float* ln2g  = (const float*)d_in[11];
    const float* ln2b  = (const float*)d_in[12];
    float* out = (float*)d_out;

    __half *qkv, *attn, *ffn, *wt;
    float *h1, *tmp;
    cudaGetSymbolAddress((void**)&qkv,  g_qkv);
    cudaGetSymbolAddress((void**)&attn, g_attn);
    cudaGetSymbolAddress((void**)&ffn,  g_ffn);
    cudaGetSymbolAddress((void**)&h1,   g_h1);
    cudaGetSymbolAddress((void**)&tmp,  g_tmp);
    cudaGetSymbolAddress((void**)&wt,   g_wt);

    cudaFuncSetAttribute(attn_h_kernel,
                         cudaFuncAttributeMaxDynamicSharedMemorySize, ATT_SMEM);

    // 0) transpose + fp16-convert weights
    transpose_h<<<dim3(3 * DMODEL / 32, DMODEL / 32), 256>>>(W_qkv, wt + WT_QKV, DMODEL, 3 * DMODEL);
    transpose_h<<<dim3(DMODEL / 32, DMODEL / 32), 256>>>(W_o, wt + WT_O, DMODEL, DMODEL);
    transpose_h<<<dim3(DFF / 32, DMODEL / 32), 256>>>(W_1, wt + WT_1, DMODEL, DFF);
    transpose_h<<<dim3(DMODEL / 32, DFF / 32), 256>>>(W_2, wt + WT_2, DFF, DMODEL);

    // 1) QKV projection: fp32 A, fp16 out
    hgemm<false, true, 0><<<dim3(3 * DMODEL / 128, ROWS / 128), 256>>>(
        X, wt + WT_QKV, b_qkv, qkv, ROWS, 3 * DMODEL, DMODEL);

    // 2) causal flash attention (fp16)
    attn_h_kernel<<<dim3(SEQ / 64, NHEADS, BATCH), 128, ATT_SMEM>>>(qkv, attn);

    // 3) output projection: fp16 A, fp32 out
    hgemm<true, false, 0><<<dim3(DMODEL / 128, ROWS / 128), 256>>>(
        attn, wt + WT_O, b_o, tmp, ROWS, DMODEL, DMODEL);

    // 4) H1 = LN(X + O)
    ln_kernel<<<ROWS, 256>>>(X, tmp, ln1g, ln1b, h1);

    // 5) FF1 + GELU: fp32 A, fp16 out
    hgemm<false, true, 1><<<dim3(DFF / 128, ROWS / 128), 256>>>(
        h1, wt + WT_1, b_1, ffn, ROWS, DFF, DMODEL);

    // 6) FF2: fp16 A, fp32 out
    hgemm<true, false, 0><<<dim3(DMODEL / 128, ROWS / 128), 256>>>(
        ffn, wt + WT_2, b_2, tmp, ROWS, DMODEL, DFF);

    // 7) out = LN(H1 + H2)
    ln_kernel<<<ROWS, 256>>>(h1, tmp, ln2g, ln2b, out);
}

// round 5
// speedup vs baseline: 7.2301x; 1.2117x over previous
#include <cuda_runtime.h>
#include <cuda_fp16.h>
#include <math.h>
#include <stdint.h>

// ---------------------------------------------------------------------------
// Problem constants
// ---------------------------------------------------------------------------
#define BATCH   2
#define SEQ     2048
#define DMODEL  1024
#define DFF     4096
#define NHEADS  16
#define DHEAD   64
#define ROWS    (BATCH * SEQ)            // 4096
#define LN_EPS  1e-5f

// ---------------------------------------------------------------------------
// Scratch — __device__ globals (no cudaMalloc allowed)
// ---------------------------------------------------------------------------
__device__ __half g_xh  [(size_t)ROWS * DMODEL];      //  8 MB fp16 X
__device__ __half g_qkv [(size_t)ROWS * 3 * DMODEL];  // 25 MB
__device__ __half g_attn[(size_t)ROWS * DMODEL];      //  8 MB
__device__ __half g_ffn [(size_t)ROWS * DFF];         // 33 MB
__device__ float  g_h1  [(size_t)ROWS * DMODEL];      // 16 MB
__device__ __half g_h1h [(size_t)ROWS * DMODEL];      //  8 MB fp16 H1
__device__ float  g_tmp [(size_t)ROWS * DMODEL];      // 16 MB
__device__ __half g_wt  [(size_t)12288 * 1024];       // 25 MB transposed fp16 weights

#define WT_QKV 0
#define WT_O   (3072 * 1024)
#define WT_1   (WT_O + 1024 * 1024)
#define WT_2   (WT_1 + 4096 * 1024)

// ---------------------------------------------------------------------------
// helpers
// ---------------------------------------------------------------------------
__device__ __forceinline__ unsigned pack2(float x, float y) {
    __half2 h = __floats2half2_rn(x, y);
    return *reinterpret_cast<unsigned*>(&h);
}

__device__ __forceinline__ void mma_f16(float c[4], const unsigned a[4],
                                        const unsigned b[2]) {
    asm volatile(
        "mma.sync.aligned.m16n8k16.row.col.f32.f16.f16.f32 "
        "{%0,%1,%2,%3},{%4,%5,%6,%7},{%8,%9},{%0,%1,%2,%3};"
        : "+f"(c[0]), "+f"(c[1]), "+f"(c[2]), "+f"(c[3])
        : "r"(a[0]), "r"(a[1]), "r"(a[2]), "r"(a[3]), "r"(b[0]), "r"(b[1]));
}

#define U32(p) (*reinterpret_cast<const unsigned*>(p))

__device__ __forceinline__ void cp16(unsigned dst, const void* src) {
    asm volatile("cp.async.cg.shared.global [%0], [%1], 16;"
                 :: "r"(dst), "l"(src));
}
#define CP_COMMIT() asm volatile("cp.async.commit_group;" ::: "memory")
#define CP_WAIT1()  asm volatile("cp.async.wait_group 1;"  ::: "memory")

__device__ __forceinline__ float gelu_exact(float x) {
    return 0.5f * x * (1.f + erff(x * 0.70710678118654752f));
}

// ---------------------------------------------------------------------------
// X -> fp16
// ---------------------------------------------------------------------------
__global__ __launch_bounds__(256)
void f2h_kernel(const float* __restrict__ in, __half* __restrict__ out)
{
    int i = blockIdx.x * 256 + threadIdx.x;
    float4 v = ((const float4*)in)[i];
    uint2 u;
    u.x = pack2(v.x, v.y);
    u.y = pack2(v.z, v.w);
    ((uint2*)out)[i] = u;
}

// ---------------------------------------------------------------------------
// Weight transpose + fp16 convert: out[C,R] = (half)in[R,C]^T
// ---------------------------------------------------------------------------
__global__ __launch_bounds__(256)
void transpose_h(const float* __restrict__ in, __half* __restrict__ out,
                 int R, int C)
{
    __shared__ float tile[32][33];
    const int c0 = blockIdx.x * 32, r0 = blockIdx.y * 32;
    const int tx = threadIdx.x & 31, ty = threadIdx.x >> 5;
#pragma unroll
    for (int i = ty; i < 32; i += 8)
        tile[i][tx] = in[(size_t)(r0 + i) * C + c0 + tx];
    __syncthreads();
#pragma unroll
    for (int i = ty; i < 32; i += 8)
        out[(size_t)(c0 + i) * R + r0 + tx] = __float2half(tile[tx][i]);
}

// ---------------------------------------------------------------------------
// fp16 GEMM, 3-stage cp.async pipeline:
// C[M,N] = act(A[M,K] @ Bt[N,K]^T + bias[N]); A,Bt fp16 row-major.
// BM=BN=128, BK=32, 256 threads (8 warps 2x4), warp tile 64x32, m16n8k16.
// smem: 3 stages x (A 128x40 + B 128x40) halfs = 61440 B dynamic.
// ---------------------------------------------------------------------------
#define PITCH 40
#define TILE_H (128 * PITCH)          // halfs per A (or B) tile
#define STAGE_H (2 * TILE_H)          // halfs per stage
#define GT_SMEM (3 * STAGE_H * 2)     // bytes

template<bool OH, int ACT>
__global__ __launch_bounds__(256)
void hgemm2(const __half* __restrict__ A, const __half* __restrict__ Bt,
            const float* __restrict__ bias, void* __restrict__ Cv,
            int M, int N, int K)
{
    extern __shared__ __half sm2[];
    unsigned sbase;
    asm("{\n\t.reg .u64 t;\n\tcvta.to.shared.u64 t, %1;\n\tcvt.u32.u64 %0, t;\n\t}"
        : "=r"(sbase) : "l"(sm2));

    const int tid = threadIdx.x, lane = tid & 31, warp = tid >> 5;
    const int wm = warp >> 2, wn = warp & 3;
    const int g = lane >> 2, tg = lane & 3;
    const int bx = blockIdx.x, by = blockIdx.y;

    const __half* Abase = A  + (size_t)(by * 128) * K;
    const __half* Bbase = Bt + (size_t)(bx * 128) * K;
    const int KT = K / 32;

    // per-thread load coords: 2 chunks of 16B per tile per operand
    const int r0c = tid >> 2, kc0 = (tid & 3) * 8;           // chunk 0
    const int r1c = (tid + 256) >> 2, kc1 = ((tid + 256) & 3) * 8;

    auto issue = [&](int kt, int slot) {
        const unsigned sa = sbase + (unsigned)(slot * STAGE_H) * 2;
        const unsigned sb = sa + (unsigned)TILE_H * 2;
        const int ko = kt * 32;
        cp16(sa + (r0c * PITCH + kc0) * 2, Abase + (size_t)r0c * K + ko + kc0);
        cp16(sa + (r1c * PITCH + kc1) * 2, Abase + (size_t)r1c * K + ko + kc1);
        cp16(sb + (r0c * PITCH + kc0) * 2, Bbase + (size_t)r0c * K + ko + kc0);
        cp16(sb + (r1c * PITCH + kc1) * 2, Bbase + (size_t)r1c * K + ko + kc1);
    };

    float c[4][4][4];
#pragma unroll
    for (int mi = 0; mi < 4; mi++)
#pragma unroll
        for (int ni = 0; ni < 4; ni++)
#pragma unroll
            for (int k = 0; k < 4; k++) c[mi][ni][k] = 0.f;

    // prologue: stages 0,1
    issue(0, 0); CP_COMMIT();
    if (KT > 1) issue(1, 1);
    CP_COMMIT();

    for (int kt = 0; kt < KT; kt++) {
        CP_WAIT1();
        __syncthreads();
        const int kn = kt + 2;
        if (kn < KT) issue(kn, kn % 3);
        CP_COMMIT();

        const __half* As = sm2 + (kt % 3) * STAGE_H;
        const __half* Bs = As + TILE_H;
#pragma unroll
        for (int ks = 0; ks < 2; ks++) {
            unsigned af[4][4], bf[4][2];
#pragma unroll
            for (int mi = 0; mi < 4; mi++) {
                const __half* ar = As + (wm * 64 + mi * 16 + g) * PITCH + ks * 16 + 2 * tg;
                af[mi][0] = U32(ar);
                af[mi][1] = U32(ar + 8 * PITCH);
                af[mi][2] = U32(ar + 8);
                af[mi][3] = U32(ar + 8 * PITCH + 8);
            }
#pragma unroll
            for (int ni = 0; ni < 4; ni++) {
                const __half* br = Bs + (wn * 32 + ni * 8 + g) * PITCH + ks * 16 + 2 * tg;
                bf[ni][0] = U32(br);
                bf[ni][1] = U32(br + 8);
            }
#pragma unroll
            for (int mi = 0; mi < 4; mi++)
#pragma unroll
                for (int ni = 0; ni < 4; ni++)
                    mma_f16(c[mi][ni], af[mi], bf[ni]);
        }
    }

    // epilogue
#pragma unroll
    for (int mi = 0; mi < 4; mi++) {
        int row = by * 128 + wm * 64 + mi * 16 + g;
#pragma unroll
        for (int ni = 0; ni < 4; ni++) {
            int col = bx * 128 + wn * 32 + ni * 8 + tg * 2;
            float b0 = bias[col], b1 = bias[col + 1];
            float v00 = c[mi][ni][0] + b0, v01 = c[mi][ni][1] + b1;
            float v10 = c[mi][ni][2] + b0, v11 = c[mi][ni][3] + b1;
            if (ACT == 1) {
                v00 = gelu_exact(v00); v01 = gelu_exact(v01);
                v10 = gelu_exact(v10); v11 = gelu_exact(v11);
            }
            if (OH) {
                __half* C = (__half*)Cv;
                *(__half2*)&C[(size_t)row * N + col] = __floats2half2_rn(v00, v01);
                *(__half2*)&C[(size_t)(row + 8) * N + col] = __floats2half2_rn(v10, v11);
            } else {
                float* C = (float*)Cv;
                *(float2*)&C[(size_t)row * N + col]       = make_float2(v00, v01);
                *(float2*)&C[(size_t)(row + 8) * N + col] = make_float2(v10, v11);
            }
        }
    }
}

// ---------------------------------------------------------------------------
// Flash attention v2: register-resident softmax (FA-2 fragment reuse).
// Block = 64 queries x head x batch, 128 threads = 4 warps (16 q each).
// K/Vt double-buffered; ONE __syncthreads per k-tile.
// ---------------------------------------------------------------------------
__global__ __launch_bounds__(128)
void attn_h2_kernel(const __half* __restrict__ qkv, __half* __restrict__ out)
{
    __shared__ __half Qs[64][72];
    __shared__ __half Ks[2][64][72];
    __shared__ __half Vt[2][64][72];     // [dim][key]

    const int qt = blockIdx.x, h = blockIdx.y, b = blockIdx.z;
    const int t = threadIdx.x, lane = t & 31, w = t >> 5;
    const int g = lane >> 2, tg = lane & 3;

    // per-thread load coords (4 x 16B chunks per 64x64 tile)
    const int lr[4] = { t >> 3, (t + 128) >> 3, (t + 256) >> 3, (t + 384) >> 3 };
    const int lc    = (t & 7) * 8;

    // Q tile
    const __half* qbase = qkv + (size_t)(b * SEQ + qt * 64) * (3 * DMODEL) + h * DHEAD;
#pragma unroll
    for (int i = 0; i < 4; i++)
        *(uint4*)&Qs[lr[i]][lc] =
            *(const uint4*)(qbase + (size_t)lr[i] * (3 * DMODEL) + lc);

    auto loadKV = [&](int kt, int buf) {
        const __half* kbase = qkv + (size_t)(b * SEQ + kt * 64) * (3 * DMODEL)
                            + DMODEL + h * DHEAD;
        const __half* vbase = kbase + DMODEL;
#pragma unroll
        for (int i = 0; i < 4; i++) {
            *(uint4*)&Ks[buf][lr[i]][lc] =
                *(const uint4*)(kbase + (size_t)lr[i] * (3 * DMODEL) + lc);
            uint4 vv = *(const uint4*)(vbase + (size_t)lr[i] * (3 * DMODEL) + lc);
            const __half* vh = (const __half*)&vv;
#pragma unroll
            for (int j = 0; j < 8; j++) Vt[buf][lc + j][lr[i]] = vh[j];
        }
    };

    loadKV(0, 0);

    float m0 = -INFINITY, m1 = -INFINITY, l0 = 0.f, l1 = 0.f;
    float co[8][4];
#pragma unroll
    for (int ni = 0; ni < 8; ni++)
#pragma unroll
        for (int k = 0; k < 4; k++) co[ni][k] = 0.f;

    const int qr = qt * 64 + w * 16 + g;

    for (int kt = 0; kt <= qt; kt++) {
        __syncthreads();
        if (kt < qt) loadKV(kt + 1, (kt + 1) & 1);
        const int buf = kt & 1;

        // ---- S = Q @ K^T ----
        float cs[8][4];
#pragma unroll
        for (int ni = 0; ni < 8; ni++)
#pragma unroll
            for (int k = 0; k < 4; k++) cs[ni][k] = 0.f;

#pragma unroll
        for (int ks = 0; ks < 4; ks++) {
            unsigned af[4];
            const __half* qr_p = &Qs[w * 16 + g][ks * 16 + 2 * tg];
            af[0] = U32(qr_p);
            af[1] = U32(qr_p + 8 * 72);
            af[2] = U32(qr_p + 8);
            af[3] = U32(qr_p + 8 * 72 + 8);
#pragma unroll
            for (int ni = 0; ni < 8; ni++) {
                unsigned bf[2];
                const __half* kp = &Ks[buf][ni * 8 + g][ks * 16 + 2 * tg];
                bf[0] = U32(kp);
                bf[1] = U32(kp + 8);
                mma_f16(cs[ni], af, bf);
            }
        }

        // scale + causal mask (in registers)
        const bool diag = (kt == qt);
#pragma unroll
        for (int ni = 0; ni < 8; ni++) {
            cs[ni][0] *= 0.125f; cs[ni][1] *= 0.125f;
            cs[ni][2] *= 0.125f; cs[ni][3] *= 0.125f;
            if (diag) {
                int kg = kt * 64 + ni * 8 + tg * 2;
                if (kg     > qr)     cs[ni][0] = -INFINITY;
                if (kg + 1 > qr)     cs[ni][1] = -INFINITY;
                if (kg     > qr + 8) cs[ni][2] = -INFINITY;
                if (kg + 1 > qr + 8) cs[ni][3] = -INFINITY;
            }
        }

        // ---- register online softmax (rows g and g+8) ----
        float mx0 = -INFINITY, mx1 = -INFINITY;
#pragma unroll
        for (int ni = 0; ni < 8; ni++) {
            mx0 = fmaxf(mx0, fmaxf(cs[ni][0], cs[ni][1]));
            mx1 = fmaxf(mx1, fmaxf(cs[ni][2], cs[ni][3]));
        }
        mx0 = fmaxf(mx0, __shfl_xor_sync(0xffffffffu, mx0, 1));
        mx0 = fmaxf(mx0, __shfl_xor_sync(0xffffffffu, mx0, 2));
        mx1 = fmaxf(mx1, __shfl_xor_sync(0xffffffffu, mx1, 1));
        mx1 = fmaxf(mx1, __shfl_xor_sync(0xffffffffu, mx1, 2));

        float mt0 = fmaxf(m0, mx0), mt1 = fmaxf(m1, mx1);
        float a0 = __expf(m0 - mt0), a1 = __expf(m1 - mt1);
        m0 = mt0; m1 = mt1;

        float ps0 = 0.f, ps1 = 0.f;
#pragma unroll
        for (int ni = 0; ni < 8; ni++) {
            cs[ni][0] = __expf(cs[ni][0] - mt0);
            cs[ni][1] = __expf(cs[ni][1] - mt0);
            cs[ni][2] = __expf(cs[ni][2] - mt1);
            cs[ni][3] = __expf(cs[ni][3] - mt1);
            ps0 += cs[ni][0] + cs[ni][1];
            ps1 += cs[ni][2] + cs[ni][3];
        }
        ps0 += __shfl_xor_sync(0xffffffffu, ps0, 1);
        ps0 += __shfl_xor_sync(0xffffffffu, ps0, 2);
        ps1 += __shfl_xor_sync(0xffffffffu, ps1, 1);
        ps1 += __shfl_xor_sync(0xffffffffu, ps1, 2);
        l0 = l0 * a0 + ps0;
        l1 = l1 * a1 + ps1;

        // rescale O
#pragma unroll
        for (int ni = 0; ni < 8; ni++) {
            co[ni][0] *= a0; co[ni][1] *= a0;
            co[ni][2] *= a1; co[ni][3] *= a1;
        }

        // ---- O += P @ V  (P packed register-direct from cs) ----
#pragma unroll
        for (int ks = 0; ks < 4; ks++) {
            unsigned af[4];
            af[0] = pack2(cs[2 * ks][0],     cs[2 * ks][1]);
            af[1] = pack2(cs[2 * ks][2],     cs[2 * ks][3]);
            af[2] = pack2(cs[2 * ks + 1][0], cs[2 * ks + 1][1]);
            af[3] = pack2(cs[2 * ks + 1][2], cs[2 * ks + 1][3]);
#pragma unroll
            for (int ni = 0; ni < 8; ni++) {
                unsigned bf[2];
                const __half* vp = &Vt[buf][ni * 8 + g][ks * 16 + 2 * tg];
                bf[0] = U32(vp);
                bf[1] = U32(vp + 8);
                mma_f16(co[ni], af, bf);
            }
        }
    }

    // normalize + store fp16
    float llo = 1.f / l0, lhi = 1.f / l1;
    int row0 = b * SEQ + qt * 64 + w * 16 + g;
    __half* ob = out + (size_t)row0 * DMODEL + h * DHEAD;
#pragma unroll
    for (int ni = 0; ni < 8; ni++) {
        int col = ni * 8 + tg * 2;
        *(__half2*)&ob[col] =
            __floats2half2_rn(co[ni][0] * llo, co[ni][1] * llo);
        *(__half2*)&ob[(size_t)8 * DMODEL + col] =
            __floats2half2_rn(co[ni][2] * lhi, co[ni][3] * lhi);
    }
}

// ---------------------------------------------------------------------------
// Fused residual add + LayerNorm (+ optional fp16 copy of output)
// ---------------------------------------------------------------------------
template<bool H16>
__global__ __launch_bounds__(256)
void ln_kernel(const float* __restrict__ A, const float* __restrict__ B,
               const float* __restrict__ g, const float* __restrict__ be,
               float* __restrict__ out, __half* __restrict__ out16)
{
    const int row = blockIdx.x;
    const size_t off = (size_t)row * DMODEL;
    const int t = threadIdx.x;

    float4 a = ((const float4*)(A + off))[t];
    float4 b = ((const float4*)(B + off))[t];
    float x0 = a.x + b.x, x1 = a.y + b.y, x2 = a.z + b.z, x3 = a.w + b.w;

    float s  = x0 + x1 + x2 + x3;
    float s2 = x0 * x0 + x1 * x1 + x2 * x2 + x3 * x3;
#pragma unroll
    for (int o = 16; o; o >>= 1) {
        s  += __shfl_xor_sync(0xffffffffu, s, o);
        s2 += __shfl_xor_sync(0xffffffffu, s2, o);
    }
    __shared__ float ws[8], ws2[8];
    if ((t & 31) == 0) { ws[t >> 5] = s; ws2[t >> 5] = s2; }
    __syncthreads();
    s = 0.f; s2 = 0.f;
#pragma unroll
    for (int i = 0; i < 8; i++) { s += ws[i]; s2 += ws2[i]; }

    const float mean = s * (1.f / DMODEL);
    const float var  = s2 * (1.f / DMODEL) - mean * mean;
    const float rstd = rsqrtf(var + LN_EPS);

    float4 gg = ((const float4*)g)[t];
    float4 bb = ((const float4*)be)[t];
    float4 y;
    y.x = (x0 - mean) * rstd * gg.x + bb.x;
    y.y = (x1 - mean) * rstd * gg.y + bb.y;
    y.z = (x2 - mean) * rstd * gg.z + bb.z;
    y.w = (x3 - mean) * rstd * gg.w + bb.w;
    ((float4*)(out + off))[t] = y;
    if (H16) {
        uint2 u;
        u.x = pack2(y.x, y.y);
        u.y = pack2(y.z, y.w);
        ((uint2*)(out16 + off))[t] = u;
    }
}

// ---------------------------------------------------------------------------
// Launcher
// ---------------------------------------------------------------------------
extern "C" void kernel_launch(void* const* d_in, const int* in_sizes, int n_in,
                              void* d_out, int out_size)
{
    const float* X     = (const float*)d_in[0];
    const float* W_qkv = (const float*)d_in[1];
    const float* b_qkv = (const float*)d_in[2];
    const float* W_o   = (const float*)d_in[3];
    const float* b_o   = (const float*)d_in[4];
    const float* W_1   = (const float*)d_in[5];
    const float* b_1   = (const float*)d_in[6];
    const float* W_2   = (const float*)d_in[7];
    const float* b_2   = (const float*)d_in[8];
    const float* ln1g  = (const float*)d_in[9];
    const float* ln1b  = (const float*)d_in[10];
    const float* ln2g  = (const float*)d_in[11];
    const float* ln2b  = (const float*)d_in[12];
    float* out = (float*)d_out;

    __half *xh, *qkv, *attn, *ffn, *h1h, *wt;
    float *h1, *tmp;
    cudaGetSymbolAddress((void**)&xh,   g_xh);
    cudaGetSymbolAddress((void**)&qkv,  g_qkv);
    cudaGetSymbolAddress((void**)&attn, g_attn);
    cudaGetSymbolAddress((void**)&ffn,  g_ffn);
    cudaGetSymbolAddress((void**)&h1,   g_h1);
    cudaGetSymbolAddress((void**)&h1h,  g_h1h);
    cudaGetSymbolAddress((void**)&tmp,  g_tmp);
    cudaGetSymbolAddress((void**)&wt,   g_wt);

    cudaFuncSetAttribute(hgemm2<true, 0>,
                         cudaFuncAttributeMaxDynamicSharedMemorySize, GT_SMEM);
    cudaFuncSetAttribute(hgemm2<false, 0>,
                         cudaFuncAttributeMaxDynamicSharedMemorySize, GT_SMEM);
    cudaFuncSetAttribute(hgemm2<true, 1>,
                         cudaFuncAttributeMaxDynamicSharedMemorySize, GT_SMEM);

    // 0) conversions
    f2h_kernel<<<ROWS * DMODEL / 1024, 256>>>(X, xh);
    transpose_h<<<dim3(3 * DMODEL / 32, DMODEL / 32), 256>>>(W_qkv, wt + WT_QKV, DMODEL, 3 * DMODEL);
    transpose_h<<<dim3(DMODEL / 32, DMODEL / 32), 256>>>(W_o, wt + WT_O, DMODEL, DMODEL);
    transpose_h<<<dim3(DFF / 32, DMODEL / 32), 256>>>(W_1, wt + WT_1, DMODEL, DFF);
    transpose_h<<<dim3(DMODEL / 32, DFF / 32), 256>>>(W_2, wt + WT_2, DFF, DMODEL);

    // 1) QKV projection
    hgemm2<true, 0><<<dim3(3 * DMODEL / 128, ROWS / 128), 256, GT_SMEM>>>(
        xh, wt + WT_QKV, b_qkv, qkv, ROWS, 3 * DMODEL, DMODEL);

    // 2) causal flash attention (register softmax)
    attn_h2_kernel<<<dim3(SEQ / 64, NHEADS, BATCH), 128>>>(qkv, attn);

    // 3) output projection -> tmp (fp32)
    hgemm2<false, 0><<<dim3(DMODEL / 128, ROWS / 128), 256, GT_SMEM>>>(
        attn, wt + WT_O, b_o, tmp, ROWS, DMODEL, DMODEL);

    // 4) H1 = LN(X + O), fp32 + fp16
    ln_kernel<true><<<ROWS, 256>>>(X, tmp, ln1g, ln1b, h1, h1h);

    // 5) FF1 + GELU
    hgemm2<true, 1><<<dim3(DFF / 128, ROWS / 128), 256, GT_SMEM>>>(
        h1h, wt + WT_1, b_1, ffn, ROWS, DFF, DMODEL);

    // 6) FF2 -> tmp (fp32)
    hgemm2<false, 0><<<dim3(DMODEL / 128, ROWS / 128), 256, GT_SMEM>>>(
        ffn, wt + WT_2, b_2, tmp, ROWS, DMODEL, DFF);

    // 7) out = LN(H1 + H2)
    ln_kernel<false><<<ROWS, 256>>>(h1, tmp, ln2g, ln2b, out, nullptr);
}

// round 6
// speedup vs baseline: 9.5331x; 1.3185x over previous
#include <cuda_runtime.h>
#include <cuda_fp16.h>
#include <math.h>
#include <stdint.h>

// ---------------------------------------------------------------------------
// Problem constants
// ---------------------------------------------------------------------------
#define BATCH   2
#define SEQ     2048
#define DMODEL  1024
#define DFF     4096
#define NHEADS  16
#define DHEAD   64
#define ROWS    (BATCH * SEQ)
#define LN_EPS  1e-5f

// ---------------------------------------------------------------------------
// Scratch — __device__ globals
// ---------------------------------------------------------------------------
__device__ __half g_xh  [(size_t)ROWS * DMODEL];
__device__ __half g_qkv [(size_t)ROWS * 3 * DMODEL];
__device__ __half g_attn[(size_t)ROWS * DMODEL];
__device__ __half g_ffn [(size_t)ROWS * DFF];
__device__ float  g_h1  [(size_t)ROWS * DMODEL];
__device__ __half g_h1h [(size_t)ROWS * DMODEL];
__device__ float  g_tmp [(size_t)ROWS * DMODEL];
__device__ __half g_wt  [(size_t)12288 * 1024];

#define WT_QKV 0
#define WT_O   (3072 * 1024)
#define WT_1   (WT_O + 1024 * 1024)
#define WT_2   (WT_1 + 4096 * 1024)

// ---------------------------------------------------------------------------
// helpers
// ---------------------------------------------------------------------------
__device__ __forceinline__ unsigned pack2(float x, float y) {
    __half2 h = __floats2half2_rn(x, y);
    return *reinterpret_cast<unsigned*>(&h);
}

__device__ __forceinline__ void mma_f16(float c[4], const unsigned a[4],
                                        const unsigned b[2]) {
    asm volatile(
        "mma.sync.aligned.m16n8k16.row.col.f32.f16.f16.f32 "
        "{%0,%1,%2,%3},{%4,%5,%6,%7},{%8,%9},{%0,%1,%2,%3};"
        : "+f"(c[0]), "+f"(c[1]), "+f"(c[2]), "+f"(c[3])
        : "r"(a[0]), "r"(a[1]), "r"(a[2]), "r"(a[3]), "r"(b[0]), "r"(b[1]));
}

__device__ __forceinline__ unsigned smaddr(const void* p) {
    unsigned a;
    asm("{\n\t.reg .u64 t;\n\tcvta.to.shared.u64 t, %1;\n\tcvt.u32.u64 %0, t;\n\t}"
        : "=r"(a) : "l"(p));
    return a;
}

__device__ __forceinline__ void ldmx4(unsigned r[4], unsigned a) {
    asm volatile("ldmatrix.sync.aligned.m8n8.x4.shared.b16 {%0,%1,%2,%3}, [%4];"
        : "=r"(r[0]), "=r"(r[1]), "=r"(r[2]), "=r"(r[3]) : "r"(a));
}
__device__ __forceinline__ void ldmx4t(unsigned r[4], unsigned a) {
    asm volatile("ldmatrix.sync.aligned.m8n8.x4.trans.shared.b16 {%0,%1,%2,%3}, [%4];"
        : "=r"(r[0]), "=r"(r[1]), "=r"(r[2]), "=r"(r[3]) : "r"(a));
}

__device__ __forceinline__ void cp16(unsigned dst, const void* src) {
    asm volatile("cp.async.cg.shared.global [%0], [%1], 16;"
                 :: "r"(dst), "l"(src));
}
#define CP_COMMIT() asm volatile("cp.async.commit_group;" ::: "memory")
#define CP_WAIT1()  asm volatile("cp.async.wait_group 1;"  ::: "memory")

__device__ __forceinline__ float gelu_exact(float x) {
    return 0.5f * x * (1.f + erff(x * 0.70710678118654752f));
}

// ---------------------------------------------------------------------------
// X -> fp16
// ---------------------------------------------------------------------------
__global__ __launch_bounds__(256)
void f2h_kernel(const float* __restrict__ in, __half* __restrict__ out)
{
    int i = blockIdx.x * 256 + threadIdx.x;
    float4 v = ((const float4*)in)[i];
    uint2 u;
    u.x = pack2(v.x, v.y);
    u.y = pack2(v.z, v.w);
    ((uint2*)out)[i] = u;
}

// ---------------------------------------------------------------------------
// Weight transpose + fp16 convert
// ---------------------------------------------------------------------------
__global__ __launch_bounds__(256)
void transpose_h(const float* __restrict__ in, __half* __restrict__ out,
                 int R, int C)
{
    __shared__ float tile[32][33];
    const int c0 = blockIdx.x * 32, r0 = blockIdx.y * 32;
    const int tx = threadIdx.x & 31, ty = threadIdx.x >> 5;
#pragma unroll
    for (int i = ty; i < 32; i += 8)
        tile[i][tx] = in[(size_t)(r0 + i) * C + c0 + tx];
    __syncthreads();
#pragma unroll
    for (int i = ty; i < 32; i += 8)
        out[(size_t)(c0 + i) * R + r0 + tx] = __float2half(tile[tx][i]);
}

// ---------------------------------------------------------------------------
// fp16 GEMM, 3-stage cp.async + ldmatrix fragments
// C[M,N] = act(A[M,K] @ Bt[N,K]^T + bias[N])
// BM=BN=128, BK=32, 256 threads (8 warps 2x4), warp tile 64x32.
// ---------------------------------------------------------------------------
#define PITCH 40
#define TILE_H (128 * PITCH)
#define STAGE_H (2 * TILE_H)
#define GT_SMEM (3 * STAGE_H * 2)

template<bool OH, int ACT>
__global__ __launch_bounds__(256)
void hgemm2(const __half* __restrict__ A, const __half* __restrict__ Bt,
            const float* __restrict__ bias, void* __restrict__ Cv,
            int M, int N, int K)
{
    extern __shared__ __half sm2[];
    const unsigned sbase = smaddr(sm2);

    const int tid = threadIdx.x, lane = tid & 31, warp = tid >> 5;
    const int wm = warp >> 2, wn = warp & 3;
    const int g = lane >> 2, tg = lane & 3;
    const int bx = blockIdx.x, by = blockIdx.y;

    const __half* Abase = A  + (size_t)(by * 128) * K;
    const __half* Bbase = Bt + (size_t)(bx * 128) * K;
    const int KT = K / 32;

    const int r0c = tid >> 2, kc0 = (tid & 3) * 8;
    const int r1c = (tid + 256) >> 2, kc1 = ((tid + 256) & 3) * 8;

    auto issue = [&](int kt, int slot) {
        const unsigned sa = sbase + (unsigned)(slot * STAGE_H) * 2;
        const unsigned sb = sa + (unsigned)TILE_H * 2;
        const int ko = kt * 32;
        cp16(sa + (r0c * PITCH + kc0) * 2, Abase + (size_t)r0c * K + ko + kc0);
        cp16(sa + (r1c * PITCH + kc1) * 2, Abase + (size_t)r1c * K + ko + kc1);
        cp16(sb + (r0c * PITCH + kc0) * 2, Bbase + (size_t)r0c * K + ko + kc0);
        cp16(sb + (r1c * PITCH + kc1) * 2, Bbase + (size_t)r1c * K + ko + kc1);
    };

    float c[4][4][4];
#pragma unroll
    for (int mi = 0; mi < 4; mi++)
#pragma unroll
        for (int ni = 0; ni < 4; ni++)
#pragma unroll
            for (int k = 0; k < 4; k++) c[mi][ni][k] = 0.f;

    issue(0, 0); CP_COMMIT();
    if (KT > 1) issue(1, 1);
    CP_COMMIT();

    // ldmatrix per-lane offsets (halfs)
    const int a_row = (lane & 15);
    const int a_col = (lane >> 4) * 8;
    const int b_row = ((lane >> 4) << 3) + (lane & 7);
    const int b_col = ((lane >> 3) & 1) * 8;

    for (int kt = 0; kt < KT; kt++) {
        CP_WAIT1();
        __syncthreads();
        const int kn = kt + 2;
        if (kn < KT) issue(kn, kn % 3);
        CP_COMMIT();

        const unsigned abase = sbase + (unsigned)((kt % 3) * STAGE_H) * 2;
        const unsigned bbase = abase + (unsigned)TILE_H * 2;

#pragma unroll
        for (int ks = 0; ks < 2; ks++) {
            unsigned af[4][4], bf[4][2];
#pragma unroll
            for (int mi = 0; mi < 4; mi++)
                ldmx4(af[mi], abase +
                      ((wm * 64 + mi * 16 + a_row) * PITCH + ks * 16 + a_col) * 2);
#pragma unroll
            for (int p = 0; p < 2; p++) {
                unsigned r[4];
                ldmx4(r, bbase +
                      ((wn * 32 + 16 * p + b_row) * PITCH + ks * 16 + b_col) * 2);
                bf[2 * p][0] = r[0]; bf[2 * p][1] = r[1];
                bf[2 * p + 1][0] = r[2]; bf[2 * p + 1][1] = r[3];
            }
#pragma unroll
            for (int mi = 0; mi < 4; mi++)
#pragma unroll
                for (int ni = 0; ni < 4; ni++)
                    mma_f16(c[mi][ni], af[mi], bf[ni]);
        }
    }

    // epilogue
#pragma unroll
    for (int mi = 0; mi < 4; mi++) {
        int row = by * 128 + wm * 64 + mi * 16 + g;
#pragma unroll
        for (int ni = 0; ni < 4; ni++) {
            int col = bx * 128 + wn * 32 + ni * 8 + tg * 2;
            float b0 = bias[col], b1 = bias[col + 1];
            float v00 = c[mi][ni][0] + b0, v01 = c[mi][ni][1] + b1;
            float v10 = c[mi][ni][2] + b0, v11 = c[mi][ni][3] + b1;
            if (ACT == 1) {
                v00 = gelu_exact(v00); v01 = gelu_exact(v01);
                v10 = gelu_exact(v10); v11 = gelu_exact(v11);
            }
            if (OH) {
                __half* C = (__half*)Cv;
                *(__half2*)&C[(size_t)row * N + col] = __floats2half2_rn(v00, v01);
                *(__half2*)&C[(size_t)(row + 8) * N + col] = __floats2half2_rn(v10, v11);
            } else {
                float* C = (float*)Cv;
                *(float2*)&C[(size_t)row * N + col]       = make_float2(v00, v01);
                *(float2*)&C[(size_t)(row + 8) * N + col] = make_float2(v10, v11);
            }
        }
    }
}

// ---------------------------------------------------------------------------
// Flash attention v3: cp.async K/V pipeline + ldmatrix fragments,
// register-resident softmax, V via ldmatrix.trans (no manual transpose).
// Block = 64 q x head x batch, 128 threads (4 warps x 16 q).
// Dynamic smem: Q + 3xK + 3xV tiles of 64x72 halfs = 64512 B.
// ---------------------------------------------------------------------------
#define QH 4608                        // halfs per 64x72 tile
#define ATT_SMEM (7 * QH * 2)

__global__ __launch_bounds__(128)
void attn_h3_kernel(const __half* __restrict__ qkv, __half* __restrict__ out)
{
    extern __shared__ __half ash[];
    const unsigned sbase = smaddr(ash);

    const int qt = gridDim.x - 1 - blockIdx.x;     // heavy tiles first
    const int h = blockIdx.y, b = blockIdx.z;
    const int t = threadIdx.x, lane = t & 31, w = t >> 5;
    const int g = lane >> 2, tg = lane & 3;

    const int lr[4] = { t >> 3, (t + 128) >> 3, (t + 256) >> 3, (t + 384) >> 3 };
    const int lc    = (t & 7) * 8;

    // Q tile (regular loads)
    const __half* qbase = qkv + (size_t)(b * SEQ + qt * 64) * (3 * DMODEL) + h * DHEAD;
#pragma unroll
    for (int i = 0; i < 4; i++)
        *(uint4*)&ash[lr[i] * 72 + lc] =
            *(const uint4*)(qbase + (size_t)lr[i] * (3 * DMODEL) + lc);

    auto issue = [&](int kt, int buf) {
        const __half* kb = qkv + (size_t)(b * SEQ + kt * 64) * (3 * DMODEL)
                         + DMODEL + h * DHEAD;
        const __half* vb = kb + DMODEL;
        const unsigned kd = sbase + (unsigned)(QH * (1 + buf)) * 2;
        const unsigned vd = sbase + (unsigned)(QH * (4 + buf)) * 2;
#pragma unroll
        for (int i = 0; i < 4; i++) {
            cp16(kd + (lr[i] * 72 + lc) * 2, kb + (size_t)lr[i] * (3 * DMODEL) + lc);
            cp16(vd + (lr[i] * 72 + lc) * 2, vb + (size_t)lr[i] * (3 * DMODEL) + lc);
        }
    };

    issue(0, 0); CP_COMMIT();
    if (qt >= 1) issue(1, 1);
    CP_COMMIT();
    __syncthreads();

    // Q fragments (hoisted)
    const int a_row = (lane & 15), a_col = (lane >> 4) * 8;
    unsigned qf[4][4];
#pragma unroll
    for (int ks = 0; ks < 4; ks++)
        ldmx4(qf[ks], sbase + ((w * 16 + a_row) * 72 + ks * 16 + a_col) * 2);

    const int b_row = ((lane >> 4) << 3) + (lane & 7);   // K frag row offset
    const int b_col = ((lane >> 3) & 1) * 8;             // K frag col offset
    const int v_row = ((lane >> 3) & 1) * 8 + (lane & 7);// V frag key offset
    const int v_col = (lane >> 4) * 8;                   // V frag dim offset

    float m0 = -INFINITY, m1 = -INFINITY, l0 = 0.f, l1 = 0.f;
    float co[8][4];
#pragma unroll
    for (int ni = 0; ni < 8; ni++)
#pragma unroll
        for (int k = 0; k < 4; k++) co[ni][k] = 0.f;

    const int qr = qt * 64 + w * 16 + g;

    for (int kt = 0; kt <= qt; kt++) {
        CP_WAIT1();
        __syncthreads();
        const int buf = kt % 3;
        const unsigned kb = sbase + (unsigned)(QH * (1 + buf)) * 2;
        const unsigned vb = sbase + (unsigned)(QH * (4 + buf)) * 2;

        // ---- S = Q @ K^T ----
        float cs[8][4];
#pragma unroll
        for (int ni = 0; ni < 8; ni++)
#pragma unroll
            for (int k = 0; k < 4; k++) cs[ni][k] = 0.f;

#pragma unroll
        for (int ks = 0; ks < 4; ks++) {
            unsigned bf[8][2];
#pragma unroll
            for (int p = 0; p < 4; p++) {
                unsigned r[4];
                ldmx4(r, kb + ((16 * p + b_row) * 72 + ks * 16 + b_col) * 2);
                bf[2 * p][0] = r[0]; bf[2 * p][1] = r[1];
                bf[2 * p + 1][0] = r[2]; bf[2 * p + 1][1] = r[3];
            }
#pragma unroll
            for (int ni = 0; ni < 8; ni++)
                mma_f16(cs[ni], qf[ks], bf[ni]);
        }

        // scale + causal mask
        const bool diag = (kt == qt);
#pragma unroll
        for (int ni = 0; ni < 8; ni++) {
            cs[ni][0] *= 0.125f; cs[ni][1] *= 0.125f;
            cs[ni][2] *= 0.125f; cs[ni][3] *= 0.125f;
            if (diag) {
                int kg = kt * 64 + ni * 8 + tg * 2;
                if (kg     > qr)     cs[ni][0] = -INFINITY;
                if (kg + 1 > qr)     cs[ni][1] = -INFINITY;
                if (kg     > qr + 8) cs[ni][2] = -INFINITY;
                if (kg + 1 > qr + 8) cs[ni][3] = -INFINITY;
            }
        }

        // ---- register online softmax ----
        float mx0 = -INFINITY, mx1 = -INFINITY;
#pragma unroll
        for (int ni = 0; ni < 8; ni++) {
            mx0 = fmaxf(mx0, fmaxf(cs[ni][0], cs[ni][1]));
            mx1 = fmaxf(mx1, fmaxf(cs[ni][2], cs[ni][3]));
        }
        mx0 = fmaxf(mx0, __shfl_xor_sync(0xffffffffu, mx0, 1));
        mx0 = fmaxf(mx0, __shfl_xor_sync(0xffffffffu, mx0, 2));
        mx1 = fmaxf(mx1, __shfl_xor_sync(0xffffffffu, mx1, 1));
        mx1 = fmaxf(mx1, __shfl_xor_sync(0xffffffffu, mx1, 2));

        float mt0 = fmaxf(m0, mx0), mt1 = fmaxf(m1, mx1);
        float a0 = __expf(m0 - mt0), a1 = __expf(m1 - mt1);
        m0 = mt0; m1 = mt1;

        float ps0 = 0.f, ps1 = 0.f;
#pragma unroll
        for (int ni = 0; ni < 8; ni++) {
            cs[ni][0] = __expf(cs[ni][0] - mt0);
            cs[ni][1] = __expf(cs[ni][1] - mt0);
            cs[ni][2] = __expf(cs[ni][2] - mt1);
            cs[ni][3] = __expf(cs[ni][3] - mt1);
            ps0 += cs[ni][0] + cs[ni][1];
            ps1 += cs[ni][2] + cs[ni][3];
        }
        ps0 += __shfl_xor_sync(0xffffffffu, ps0, 1);
        ps0 += __shfl_xor_sync(0xffffffffu, ps0, 2);
        ps1 += __shfl_xor_sync(0xffffffffu, ps1, 1);
        ps1 += __shfl_xor_sync(0xffffffffu, ps1, 2);
        l0 = l0 * a0 + ps0;
        l1 = l1 * a1 + ps1;

#pragma unroll
        for (int ni = 0; ni < 8; ni++) {
            co[ni][0] *= a0; co[ni][1] *= a0;
            co[ni][2] *= a1; co[ni][3] *= a1;
        }

        // ---- O += P @ V (V fragments via ldmatrix.trans) ----
#pragma unroll
        for (int ks = 0; ks < 4; ks++) {
            unsigned af[4];
            af[0] = pack2(cs[2 * ks][0],     cs[2 * ks][1]);
            af[1] = pack2(cs[2 * ks][2],     cs[2 * ks][3]);
            af[2] = pack2(cs[2 * ks + 1][0], cs[2 * ks + 1][1]);
            af[3] = pack2(cs[2 * ks + 1][2], cs[2 * ks + 1][3]);
            unsigned bf[8][2];
#pragma unroll
            for (int p = 0; p < 4; p++) {
                unsigned r[4];
                ldmx4t(r, vb + ((ks * 16 + v_row) * 72 + 16 * p + v_col) * 2);
                bf[2 * p][0] = r[0]; bf[2 * p][1] = r[1];
                bf[2 * p + 1][0] = r[2]; bf[2 * p + 1][1] = r[3];
            }
#pragma unroll
            for (int ni = 0; ni < 8; ni++)
                mma_f16(co[ni], af, bf[ni]);
        }

        // prefetch tile kt+2 (buffer (kt+2)%3 is free: all warps passed the
        // barrier above, so compute of kt-1 — which read that buffer — is done)
        if (kt + 2 <= qt) issue(kt + 2, (kt + 2) % 3);
        CP_COMMIT();
    }

    // normalize + store fp16
    float llo = 1.f / l0, lhi = 1.f / l1;
    int row0 = b * SEQ + qt * 64 + w * 16 + g;
    __half* ob = out + (size_t)row0 * DMODEL + h * DHEAD;
#pragma unroll
    for (int ni = 0; ni < 8; ni++) {
        int col = ni * 8 + tg * 2;
        *(__half2*)&ob[col] =
            __floats2half2_rn(co[ni][0] * llo, co[ni][1] * llo);
        *(__half2*)&ob[(size_t)8 * DMODEL + col] =
            __floats2half2_rn(co[ni][2] * lhi, co[ni][3] * lhi);
    }
}

// ---------------------------------------------------------------------------
// Fused residual add + LayerNorm (+ optional fp16 copy)
// ---------------------------------------------------------------------------
template<bool H16>
__global__ __launch_bounds__(256)
void ln_kernel(const float* __restrict__ A, const float* __restrict__ B,
               const float* __restrict__ g, const float* __restrict__ be,
               float* __restrict__ out, __half* __restrict__ out16)
{
    const int row = blockIdx.x;
    const size_t off = (size_t)row * DMODEL;
    const int t = threadIdx.x;

    float4 a = ((const float4*)(A + off))[t];
    float4 b = ((const float4*)(B + off))[t];
    float x0 = a.x + b.x, x1 = a.y + b.y, x2 = a.z + b.z, x3 = a.w + b.w;

    float s  = x0 + x1 + x2 + x3;
    float s2 = x0 * x0 + x1 * x1 + x2 * x2 + x3 * x3;
#pragma unroll
    for (int o = 16; o; o >>= 1) {
        s  += __shfl_xor_sync(0xffffffffu, s, o);
        s2 += __shfl_xor_sync(0xffffffffu, s2, o);
    }
    __shared__ float ws[8], ws2[8];
    if ((t & 31) == 0) { ws[t >> 5] = s; ws2[t >> 5] = s2; }
    __syncthreads();
    s = 0.f; s2 = 0.f;
#pragma unroll
    for (int i = 0; i < 8; i++) { s += ws[i]; s2 += ws2[i]; }

    const float mean = s * (1.f / DMODEL);
    const float var  = s2 * (1.f / DMODEL) - mean * mean;
    const float rstd = rsqrtf(var + LN_EPS);

    float4 gg = ((const float4*)g)[t];
    float4 bb = ((const float4*)be)[t];
    float4 y;
    y.x = (x0 - mean) * rstd * gg.x + bb.x;
    y.y = (x1 - mean) * rstd * gg.y + bb.y;
    y.z = (x2 - mean) * rstd * gg.z + bb.z;
    y.w = (x3 - mean) * rstd * gg.w + bb.w;
    ((float4*)(out + off))[t] = y;
    if (H16) {
        uint2 u;
        u.x = pack2(y.x, y.y);
        u.y = pack2(y.z, y.w);
        ((uint2*)(out16 + off))[t] = u;
    }
}

// ---------------------------------------------------------------------------
// Launcher
// ---------------------------------------------------------------------------
extern "C" void kernel_launch(void* const* d_in, const int* in_sizes, int n_in,
                              void* d_out, int out_size)
{
    const float* X     = (const float*)d_in[0];
    const float* W_qkv = (const float*)d_in[1];
    const float* b_qkv = (const float*)d_in[2];
    const float* W_o   = (const float*)d_in[3];
    const float* b_o   = (const float*)d_in[4];
    const float* W_1   = (const float*)d_in[5];
    const float* b_1   = (const float*)d_in[6];
    const float* W_2   = (const float*)d_in[7];
    const float* b_2   = (const float*)d_in[8];
    const float* ln1g  = (const float*)d_in[9];
    const float* ln1b  = (const float*)d_in[10];
    const float* ln2g  = (const float*)d_in[11];
    const float* ln2b  = (const float*)d_in[12];
    float* out = (float*)d_out;

    __half *xh, *qkv, *attn, *ffn, *h1h, *wt;
    float *h1, *tmp;
    cudaGetSymbolAddress((void**)&xh,   g_xh);
    cudaGetSymbolAddress((void**)&qkv,  g_qkv);
    cudaGetSymbolAddress((void**)&attn, g_attn);
    cudaGetSymbolAddress((void**)&ffn,  g_ffn);
    cudaGetSymbolAddress((void**)&h1,   g_h1);
    cudaGetSymbolAddress((void**)&h1h,  g_h1h);
    cudaGetSymbolAddress((void**)&tmp,  g_tmp);
    cudaGetSymbolAddress((void**)&wt,   g_wt);

    cudaFuncSetAttribute(hgemm2<true, 0>,
                         cudaFuncAttributeMaxDynamicSharedMemorySize, GT_SMEM);
    cudaFuncSetAttribute(hgemm2<false, 0>,
                         cudaFuncAttributeMaxDynamicSharedMemorySize, GT_SMEM);
    cudaFuncSetAttribute(hgemm2<true, 1>,
                         cudaFuncAttributeMaxDynamicSharedMemorySize, GT_SMEM);
    cudaFuncSetAttribute(attn_h3_kernel,
                         cudaFuncAttributeMaxDynamicSharedMemorySize, ATT_SMEM);

    // 0) conversions
    f2h_kernel<<<ROWS * DMODEL / 1024, 256>>>(X, xh);
    transpose_h<<<dim3(3 * DMODEL / 32, DMODEL / 32), 256>>>(W_qkv, wt + WT_QKV, DMODEL, 3 * DMODEL);
    transpose_h<<<dim3(DMODEL / 32, DMODEL / 32), 256>>>(W_o, wt + WT_O, DMODEL, DMODEL);
    transpose_h<<<dim3(DFF / 32, DMODEL / 32), 256>>>(W_1, wt + WT_1, DMODEL, DFF);
    transpose_h<<<dim3(DMODEL / 32, DFF / 32), 256>>>(W_2, wt + WT_2, DFF, DMODEL);

    // 1) QKV projection
    hgemm2<true, 0><<<dim3(3 * DMODEL / 128, ROWS / 128), 256, GT_SMEM>>>(
        xh, wt + WT_QKV, b_qkv, qkv, ROWS, 3 * DMODEL, DMODEL);

    // 2) causal flash attention
    attn_h3_kernel<<<dim3(SEQ / 64, NHEADS, BATCH), 128, ATT_SMEM>>>(qkv, attn);

    // 3) output projection -> tmp (fp32)
    hgemm2<false, 0><<<dim3(DMODEL / 128, ROWS / 128), 256, GT_SMEM>>>(
        attn, wt + WT_O, b_o, tmp, ROWS, DMODEL, DMODEL);

    // 4) H1 = LN(X + O), fp32 + fp16
    ln_kernel<true><<<ROWS, 256>>>(X, tmp, ln1g, ln1b, h1, h1h);

    // 5) FF1 + GELU
    hgemm2<true, 1><<<dim3(DFF / 128, ROWS / 128), 256, GT_SMEM>>>(
        h1h, wt + WT_1, b_1, ffn, ROWS, DFF, DMODEL);

    // 6) FF2 -> tmp (fp32)
    hgemm2<false, 0><<<dim3(DMODEL / 128, ROWS / 128), 256, GT_SMEM>>>(
        ffn, wt + WT_2, b_2, tmp, ROWS, DMODEL, DFF);

    // 7) out = LN(H1 + H2)
    ln_kernel<false><<<ROWS, 256>>>(h1, tmp, ln2g, ln2b, out, nullptr);
}